// round 10
// baseline (speedup 1.0000x reference)
#include <cuda_runtime.h>
#include <cuda_bf16.h>
#include <cstdint>

// GNN_84421877170708: 4-layer GCL GNN. Round 9:
//  - edge kernel at 4 CTAs/SM (reg-trimmed pairwise gather, XSTR 82->78)
//  - all W1 repacks hoisted to one upfront kernel; per-layer prep = agg zero

#define N_NODES 50000
#define E_EDGES 800000
#define IN_NF   64
#define HID     128
#define EH      64
#define OUT_NF  64
#define L_LAYERS 4
#define ET      128
#define XSTR    78
#define SCAN_BLOCKS ((N_NODES + 255) / 256)

__device__ float g_h[N_NODES * HID];
__device__ float g_agg[N_NODES * EH];
__device__ float g_z[N_NODES * HID];
__device__ float g_wcat[L_LAYERS * HID * HID];
__device__ float g_bcat[L_LAYERS * HID];

__device__ int g_deg[N_NODES];
__device__ int g_base[N_NODES];
__device__ int g_cursor[N_NODES];
__device__ int g_bsums[256];
__device__ int g_srow[E_EDGES];
__device__ int g_scol[E_EDGES];

using u64 = unsigned long long;
using u32 = unsigned int;

__device__ __forceinline__ float silu(float v) {
    float h = 0.5f * v, t;
    asm("tanh.approx.f32 %0, %1;" : "=f"(t) : "f"(h));
    return fmaf(h, t, h);
}
__device__ __forceinline__ u32 f2tf32(float f) {
    u32 r; asm("cvt.rna.tf32.f32 %0, %1;" : "=r"(r) : "f"(f)); return r;
}
__device__ __forceinline__ float tf32f(float f) {
    return __uint_as_float(f2tf32(f));
}
__device__ __forceinline__ void mma_tf32(float* c, u32 a0, u32 a1, u32 a2, u32 a3,
                                         u32 b0, u32 b1) {
    asm volatile(
        "mma.sync.aligned.m16n8k8.row.col.f32.tf32.tf32.f32 "
        "{%0,%1,%2,%3}, {%4,%5,%6,%7}, {%8,%9}, {%0,%1,%2,%3};"
        : "+f"(c[0]), "+f"(c[1]), "+f"(c[2]), "+f"(c[3])
        : "r"(a0), "r"(a1), "r"(a2), "r"(a3), "r"(b0), "r"(b1));
}
__device__ __forceinline__ void red4(float* p, float a, float b, float c, float d) {
    asm volatile("red.global.add.v4.f32 [%0], {%1,%2,%3,%4};"
                 :: "l"(p), "f"(a), "f"(b), "f"(c), "f"(d) : "memory");
}
__device__ __forceinline__ void ffma2(u64& acc, u64 x, u64 w) {
    asm("fma.rn.f32x2 %0, %1, %2, %0;" : "+l"(acc) : "l"(x), "l"(w));
}
__device__ __forceinline__ u64 pack2(float x) {
    u64 r; asm("mov.b64 %0, {%1, %1};" : "=l"(r) : "f"(x)); return r;
}
__device__ __forceinline__ u64 packf2(float a, float b) {
    u64 r; asm("mov.b64 %0, {%1, %2};" : "=l"(r) : "f"(a), "f"(b)); return r;
}
__device__ __forceinline__ float2 unpack2(u64 v) {
    float2 r; asm("mov.b64 {%0, %1}, %2;" : "=f"(r.x), "=f"(r.y) : "l"(v)); return r;
}

// ---------------------------------------------------------------------------
// counting sort of edges by row
// ---------------------------------------------------------------------------
__global__ void k_zero_deg() {
    int i = blockIdx.x * 256 + threadIdx.x;
    if (i < N_NODES) { g_deg[i] = 0; g_cursor[i] = 0; }
}
__global__ void k_hist(const int* __restrict__ edges) {
    int e = blockIdx.x * 256 + threadIdx.x;
    if (e < E_EDGES) atomicAdd(&g_deg[edges[e]], 1);
}
__global__ void k_scan1() {
    __shared__ int s[256];
    int i = blockIdx.x * 256 + threadIdx.x;
    int v = (i < N_NODES) ? g_deg[i] : 0;
    s[threadIdx.x] = v;
    __syncthreads();
#pragma unroll
    for (int o = 1; o < 256; o <<= 1) {
        int t = (threadIdx.x >= o) ? s[threadIdx.x - o] : 0;
        __syncthreads();
        s[threadIdx.x] += t;
        __syncthreads();
    }
    if (i < N_NODES) g_base[i] = s[threadIdx.x] - v;
    if (threadIdx.x == 255) g_bsums[blockIdx.x] = s[255];
}
__global__ void k_scan2() {
    __shared__ int s[256];
    int i = threadIdx.x;
    int v = (i < SCAN_BLOCKS) ? g_bsums[i] : 0;
    s[i] = v;
    __syncthreads();
#pragma unroll
    for (int o = 1; o < 256; o <<= 1) {
        int t = (i >= o) ? s[i - o] : 0;
        __syncthreads();
        s[i] += t;
        __syncthreads();
    }
    g_bsums[i] = s[i] - v;
}
__global__ void k_scan3() {
    int i = blockIdx.x * 256 + threadIdx.x;
    if (i < N_NODES) g_base[i] += g_bsums[blockIdx.x];
}
__global__ void k_sort_scatter(const int* __restrict__ edges) {
    int e = blockIdx.x * 256 + threadIdx.x;
    if (e < E_EDGES) {
        int r = edges[e], c = edges[E_EDGES + e];
        int pos = g_base[r] + atomicAdd(&g_cursor[r], 1);
        g_srow[pos] = r;
        g_scol[pos] = c;
    }
}

// ---------------------------------------------------------------------------
// repack ALL layers' W1 -> g_wcat[l][128x128], g_bcat[l] = [b1|0]  (once)
// ---------------------------------------------------------------------------
__global__ void k_repack(const float* __restrict__ eW1, const float* __restrict__ eb1) {
    int i = blockIdx.x * 256 + threadIdx.x;
    if (i < L_LAYERS * HID * HID) {
        int l = i >> 14, r = i & 16383;
        int k = r >> 7, j = r & 127;
        const float* w = eW1 + l * 2 * HID * EH;
        g_wcat[i] = (j < 64) ? w[k * 64 + j] : w[(k + 128) * 64 + (j - 64)];
    }
    if (i < L_LAYERS * HID) {
        int l = i >> 7, j = i & 127;
        g_bcat[i] = (j < 64) ? eb1[l * EH + j] : 0.f;
    }
}

__global__ void k_zero_agg() {
    int i = blockIdx.x * 256 + threadIdx.x;
    if (i < N_NODES * EH / 4)
        ((float4*)g_agg)[i] = make_float4(0.f, 0.f, 0.f, 0.f);
}

// ---------------------------------------------------------------------------
// node_mma (tf32): out[:, yoff:+64] = act(concat(in1,in2) @ W[:, yoff:+64] + b)
// ---------------------------------------------------------------------------
template<int KDIM, int W1IN, bool DO_SILU>
__global__ void __launch_bounds__(256, 2) node_mma(
    const float* __restrict__ in1, const float* __restrict__ in2,
    const float* __restrict__ W, const float* __restrict__ b,
    float* __restrict__ out)
{
    constexpr int NSTEP = KDIM / 8;
    extern __shared__ float sm[];
    float* bs = sm;
    float* X  = sm + 64;
    float* Bp = X + 128 * XSTR;

    const int tid  = threadIdx.x;
    const int warp = tid >> 5, lane = tid & 31;
    const int g    = lane >> 2, tig = lane & 3;
    const int yoff = blockIdx.y * 64;

    for (int i = tid; i < NSTEP * 4 * 32; i += 256) {
        int s  = i >> 7;
        int gp = (i >> 5) & 3;
        int ln = i & 31;
        int gg = ln >> 2, tt = ln & 3;
        int k0 = s * 8;
        int nA = yoff + gp * 16 + (gg >> 1) * 4 + (gg & 1);
        int nB = nA + 2;
        float4 v;
        v.x = tf32f(W[(size_t)(k0 + tt)     * HID + nA]);
        v.y = tf32f(W[(size_t)(k0 + tt + 4) * HID + nA]);
        v.z = tf32f(W[(size_t)(k0 + tt)     * HID + nB]);
        v.w = tf32f(W[(size_t)(k0 + tt + 4) * HID + nB]);
        *(float4*)&Bp[i * 4] = v;
    }
    if (tid < 64) bs[tid] = b[yoff + tid];

    const float* xlo = X + (warp * 16 + g) * XSTR + tig * 2;
    const float* xhi = xlo + 8 * XSTR;
    const int e  = tid >> 1;
    const int hf = tid & 1;

    const int NTILES = (N_NODES + 127) / 128;
    for (int t = blockIdx.x; t < NTILES; t += gridDim.x) {
        const int tb = t * 128;
        int node = tb + e;
        if (node >= N_NODES) node = 0;

        float acc[8][4];
#pragma unroll
        for (int a = 0; a < 8; a++)
#pragma unroll
            for (int c = 0; c < 4; c++) acc[a][c] = 0.f;

#pragma unroll
        for (int c0 = 0; c0 < KDIM; c0 += 64) {
            __syncthreads();
            {
                const int kb = c0 + hf * 32;
                const float4* src;
                if (KDIM == W1IN || kb < W1IN)
                    src = (const float4*)(in1 + (size_t)node * W1IN + kb);
                else
                    src = (const float4*)(in2 + (size_t)node * (KDIM - W1IN) + (kb - W1IN));
                float* xr = X + e * XSTR + hf * 32;
#pragma unroll
                for (int bb = 0; bb < 4; bb++) {
                    float4 x0 = src[2 * bb];
                    float4 x1 = src[2 * bb + 1];
                    *(float2*)&xr[bb * 8 + 0] = make_float2(tf32f(x0.x), tf32f(x1.x));
                    *(float2*)&xr[bb * 8 + 2] = make_float2(tf32f(x0.y), tf32f(x1.y));
                    *(float2*)&xr[bb * 8 + 4] = make_float2(tf32f(x0.z), tf32f(x1.z));
                    *(float2*)&xr[bb * 8 + 6] = make_float2(tf32f(x0.w), tf32f(x1.w));
                }
            }
            __syncthreads();

#pragma unroll
            for (int s8 = 0; s8 < 8; s8++) {
                const int s = (c0 >> 3) + s8;
                float2 alo = *(const float2*)(xlo + s8 * 8);
                float2 ahi = *(const float2*)(xhi + s8 * 8);
                u32 a0 = __float_as_uint(alo.x), a1 = __float_as_uint(ahi.x);
                u32 a2 = __float_as_uint(alo.y), a3 = __float_as_uint(ahi.y);
#pragma unroll
                for (int gp = 0; gp < 4; gp++) {
                    float4 bv = *(const float4*)&Bp[((s * 4 + gp) * 32 + lane) * 4];
                    mma_tf32(acc[gp * 2 + 0], a0, a1, a2, a3,
                             __float_as_uint(bv.x), __float_as_uint(bv.y));
                    mma_tf32(acc[gp * 2 + 1], a0, a1, a2, a3,
                             __float_as_uint(bv.z), __float_as_uint(bv.w));
                }
            }
        }

        {
            int r0 = tb + warp * 16 + g;
            int r1 = r0 + 8;
#pragma unroll
            for (int gp = 0; gp < 4; gp++) {
                int c0 = gp * 16 + tig * 4;
                float4 v0 = make_float4(acc[gp*2][0]   + bs[c0],
                                        acc[gp*2][1]   + bs[c0+1],
                                        acc[gp*2+1][0] + bs[c0+2],
                                        acc[gp*2+1][1] + bs[c0+3]);
                float4 v1 = make_float4(acc[gp*2][2]   + bs[c0],
                                        acc[gp*2][3]   + bs[c0+1],
                                        acc[gp*2+1][2] + bs[c0+2],
                                        acc[gp*2+1][3] + bs[c0+3]);
                if (DO_SILU) {
                    v0.x = silu(v0.x); v0.y = silu(v0.y); v0.z = silu(v0.z); v0.w = silu(v0.w);
                    v1.x = silu(v1.x); v1.y = silu(v1.y); v1.z = silu(v1.z); v1.w = silu(v1.w);
                }
                if (r0 < N_NODES) *(float4*)(out + (size_t)r0 * HID + yoff + c0) = v0;
                if (r1 < N_NODES) *(float4*)(out + (size_t)r1 * HID + yoff + c0) = v1;
            }
        }
    }
}

// ---------------------------------------------------------------------------
// node_gemm3 (fp32, residual nb + embeddings)
// ---------------------------------------------------------------------------
template<int KDIM, int W1IN, int NOUT_TOTAL, bool DO_SILU, bool DO_RES>
__global__ void __launch_bounds__(256, 2) node_gemm3(
    const float* __restrict__ in1, const float* __restrict__ in2,
    const float* __restrict__ W, const float* __restrict__ b,
    float* __restrict__ out)
{
    extern __shared__ float fsmem[];
    float* ws = fsmem;
    float* bs = ws + KDIM * 64;
    float* stg = bs + 64;

    const int tid  = threadIdx.x;
    const int warp = tid >> 5;
    const int lane = tid & 31;
    const int yoff = blockIdx.y * 64;

    for (int i = tid * 4; i < KDIM * 64; i += 1024) {
        int k = i >> 6, j = i & 63;
        *(float4*)&ws[i] = *(const float4*)(W + (size_t)k * NOUT_TOTAL + yoff + j);
    }
    if (tid < 64) bs[tid] = b[yoff + tid];
    __syncthreads();

    float* xs = stg + warp * (64 * 16);
    const int p    = lane >> 2;
    const int q    = lane & 3;
    const int m    = lane >> 1;
    const int half = lane & 1;

    u64 biasr[4];
#pragma unroll
    for (int g = 0; g < 4; g++)
        biasr[g] = packf2(bs[p * 8 + 2 * g], bs[p * 8 + 2 * g + 1]);

    const int gw     = blockIdx.x * 8 + warp;
    const int nwarps = gridDim.x * 8;
    const int ntiles = N_NODES / 16;

    for (int t = gw; t < ntiles; t += nwarps) {
        const int node = t * 16 + m;
        const float* s1 = in1 + (size_t)node * W1IN;
        const float* s2 = (KDIM > W1IN) ? in2 + (size_t)node * (KDIM - W1IN) : nullptr;

        u64 acc[4][4];
#pragma unroll
        for (int d = 0; d < 4; d++)
#pragma unroll
            for (int g = 0; g < 4; g++) acc[d][g] = biasr[g];

#pragma unroll
        for (int c0 = 0; c0 < KDIM; c0 += 64) {
            __syncwarp();
#pragma unroll
            for (int i = 0; i < 8; i++) {
                int kk = c0 + half * 32 + i * 4;
                float4 v;
                if (KDIM == W1IN || kk < W1IN) v = *(const float4*)(s1 + kk);
                else                           v = *(const float4*)(s2 + (kk - W1IN));
                int kl = kk - c0;
                xs[(kl + 0) * 16 + m] = v.x;
                xs[(kl + 1) * 16 + m] = v.y;
                xs[(kl + 2) * 16 + m] = v.z;
                xs[(kl + 3) * 16 + m] = v.w;
            }
            __syncwarp();

#pragma unroll 4
            for (int k = 0; k < 64; k++) {
                float4 xv = *(const float4*)&xs[k * 16 + q * 4];
                const ulonglong2* wp = (const ulonglong2*)(ws + (c0 + k) * 64 + p * 8);
                ulonglong2 wa = wp[0];
                ulonglong2 wb = wp[1];
                u64 xp[4] = {pack2(xv.x), pack2(xv.y), pack2(xv.z), pack2(xv.w)};
#pragma unroll
                for (int d = 0; d < 4; d++) {
                    ffma2(acc[d][0], xp[d], wa.x);
                    ffma2(acc[d][1], xp[d], wa.y);
                    ffma2(acc[d][2], xp[d], wb.x);
                    ffma2(acc[d][3], xp[d], wb.y);
                }
            }
        }

#pragma unroll
        for (int d = 0; d < 4; d++) {
            int nn = t * 16 + q * 4 + d;
            float* dst = out + (size_t)nn * NOUT_TOTAL + yoff + p * 8;
#pragma unroll
            for (int g = 0; g < 2; g++) {
                float2 a = unpack2(acc[d][2 * g]);
                float2 c = unpack2(acc[d][2 * g + 1]);
                float4 v = make_float4(a.x, a.y, c.x, c.y);
                if (DO_SILU) {
                    v.x = silu(v.x); v.y = silu(v.y);
                    v.z = silu(v.z); v.w = silu(v.w);
                }
                if (DO_RES) {
                    float4 r = *(const float4*)(dst + g * 4);
                    v.x += r.x; v.y += r.y; v.z += r.z; v.w += r.w;
                }
                *(float4*)(dst + g * 4) = v;
            }
        }
    }
}

// ---------------------------------------------------------------------------
// Edge kernel: sorted edges; pairwise gather+silu -> tf32 mma MLP2 ->
// segmented reduction -> red4 per run. 4 CTAs/SM.
// ---------------------------------------------------------------------------
#define SM_IDX  0
#define SM_B2S  128
#define SM_X2   192
#define SM_B2P  (192 + 128 * XSTR)
#define SM_EDGE_FLOATS (SM_B2P + 8 * 4 * 32 * 4)
#define SM_EDGE_BYTES  (SM_EDGE_FLOATS * 4)   // 57088

__global__ void __launch_bounds__(256, 4)
edge_kernel2(const int* __restrict__ srow, const int* __restrict__ scol,
             const float* __restrict__ P,
             const float* __restrict__ W2, const float* __restrict__ b2)
{
    extern __shared__ float sm[];
    int*   idxs = (int*)sm;
    float* b2s  = sm + SM_B2S;
    float* X2   = sm + SM_X2;
    float* B2p  = sm + SM_B2P;

    const int tid  = threadIdx.x;
    const int warp = tid >> 5, lane = tid & 31;
    const int g    = lane >> 2, tig = lane & 3;

    for (int i = tid; i < 8 * 4 * 32; i += 256) {
        int s  = i >> 7;
        int gp = (i >> 5) & 3;
        int ln = i & 31;
        int gg = ln >> 2, tt = ln & 3;
        int k0 = s * 8;
        int nA = gp * 16 + (gg >> 1) * 4 + (gg & 1);
        int nB = nA + 2;
        float4 v;
        v.x = tf32f(W2[(k0 + tt)     * 64 + nA]);
        v.y = tf32f(W2[(k0 + tt + 4) * 64 + nA]);
        v.z = tf32f(W2[(k0 + tt)     * 64 + nB]);
        v.w = tf32f(W2[(k0 + tt + 4) * 64 + nB]);
        *(float4*)&B2p[i * 4] = v;
    }
    if (tid < 64) b2s[tid] = b2[tid];
    __syncthreads();

    const float* xlo = X2 + (warp * 16 + g) * XSTR + tig * 2;
    const float* xhi = xlo + 8 * XSTR;
    const int e_lo = warp * 16 + g;
    const int e_hi = e_lo + 8;
    const int qd = tid & 15;
    const int sp = tid >> 4;

    for (int t = blockIdx.x; t < E_EDGES / ET; t += gridDim.x) {
        // ---- pairwise gather + silu -> X2 (frag-interleaved tf32) ----
        {
            int e = tid >> 1, half = tid & 1;
            int row  = srow[t * ET + e];
            int coln = scol[t * ET + e];
            if (half == 0) idxs[e] = row;
            const float4* pa = (const float4*)(P + (size_t)row  * HID + half * 32);
            const float4* pb = (const float4*)(P + (size_t)coln * HID + 64 + half * 32);
            float* xr = X2 + e * XSTR + half * 32;
#pragma unroll
            for (int bb = 0; bb < 4; bb++) {
                float4 x0 = pa[2 * bb],     y0 = pb[2 * bb];
                float4 x1 = pa[2 * bb + 1], y1 = pb[2 * bb + 1];
                *(float2*)&xr[bb * 8 + 0] = make_float2(tf32f(silu(x0.x + y0.x)),
                                                        tf32f(silu(x1.x + y1.x)));
                *(float2*)&xr[bb * 8 + 2] = make_float2(tf32f(silu(x0.y + y0.y)),
                                                        tf32f(silu(x1.y + y1.y)));
                *(float2*)&xr[bb * 8 + 4] = make_float2(tf32f(silu(x0.z + y0.z)),
                                                        tf32f(silu(x1.z + y1.z)));
                *(float2*)&xr[bb * 8 + 6] = make_float2(tf32f(silu(x0.w + y0.w)),
                                                        tf32f(silu(x1.w + y1.w)));
            }
        }
        __syncthreads();

        // ---- MLP2 MMA ----
        float acc[8][4];
#pragma unroll
        for (int a = 0; a < 8; a++)
#pragma unroll
            for (int c = 0; c < 4; c++) acc[a][c] = 0.f;

#pragma unroll
        for (int s = 0; s < 8; s++) {
            float2 alo = *(const float2*)(xlo + s * 8);
            float2 ahi = *(const float2*)(xhi + s * 8);
            u32 a0 = __float_as_uint(alo.x), a1 = __float_as_uint(ahi.x);
            u32 a2 = __float_as_uint(alo.y), a3 = __float_as_uint(ahi.y);
#pragma unroll
            for (int gp = 0; gp < 4; gp++) {
                float4 bv = *(const float4*)&B2p[((s * 4 + gp) * 32 + lane) * 4];
                mma_tf32(acc[gp * 2 + 0], a0, a1, a2, a3,
                         __float_as_uint(bv.x), __float_as_uint(bv.y));
                mma_tf32(acc[gp * 2 + 1], a0, a1, a2, a3,
                         __float_as_uint(bv.z), __float_as_uint(bv.w));
            }
        }
        __syncthreads();

        // ---- write silu(D2 + b2) back into X2 as R[e][0..63] ----
        {
            float* rlo = X2 + e_lo * XSTR;
            float* rhi = X2 + e_hi * XSTR;
#pragma unroll
            for (int gp = 0; gp < 4; gp++) {
                int c0 = gp * 16 + tig * 4;
                *(float2*)&rlo[c0]     = make_float2(silu(acc[gp*2][0]   + b2s[c0]),
                                                     silu(acc[gp*2][1]   + b2s[c0+1]));
                *(float2*)&rlo[c0 + 2] = make_float2(silu(acc[gp*2+1][0] + b2s[c0+2]),
                                                     silu(acc[gp*2+1][1] + b2s[c0+3]));
                *(float2*)&rhi[c0]     = make_float2(silu(acc[gp*2][2]   + b2s[c0]),
                                                     silu(acc[gp*2][3]   + b2s[c0+1]));
                *(float2*)&rhi[c0 + 2] = make_float2(silu(acc[gp*2+1][2] + b2s[c0+2]),
                                                     silu(acc[gp*2+1][3] + b2s[c0+3]));
            }
        }
        __syncthreads();

        // ---- segmented reduction: thread (qd, sp) walks 8 edges for 4 cols ----
        {
            int e0 = sp * 8;
            int cur = idxs[e0];
            const float* r = X2 + e0 * XSTR + qd * 4;
            float2 a01 = *(const float2*)(r);
            float2 a23 = *(const float2*)(r + 2);
            float s0 = a01.x, s1 = a01.y, s2 = a23.x, s3 = a23.y;
#pragma unroll
            for (int j = 1; j < 8; j++) {
                int rw = idxs[e0 + j];
                const float* rr = X2 + (e0 + j) * XSTR + qd * 4;
                float2 b01 = *(const float2*)(rr);
                float2 b23 = *(const float2*)(rr + 2);
                if (rw != cur) {
                    red4(g_agg + (size_t)cur * EH + qd * 4, s0, s1, s2, s3);
                    cur = rw;
                    s0 = b01.x; s1 = b01.y; s2 = b23.x; s3 = b23.y;
                } else {
                    s0 += b01.x; s1 += b01.y; s2 += b23.x; s3 += b23.y;
                }
            }
            red4(g_agg + (size_t)cur * EH + qd * 4, s0, s1, s2, s3);
        }
        __syncthreads();
    }
}

// ---------------------------------------------------------------------------
extern "C" void kernel_launch(void* const* d_in, const int* in_sizes, int n_in,
                              void* d_out, int out_size)
{
    const float* h_in  = (const float*)d_in[0];
    const int*   edges = (const int*)d_in[1];
    const float* W_in  = (const float*)d_in[2];
    const float* b_in  = (const float*)d_in[3];
    const float* eW1   = (const float*)d_in[4];
    const float* eb1   = (const float*)d_in[5];
    const float* eW2   = (const float*)d_in[6];
    const float* eb2   = (const float*)d_in[7];
    const float* nW1   = (const float*)d_in[8];
    const float* nb1   = (const float*)d_in[9];
    const float* nW2   = (const float*)d_in[10];
    const float* nb2   = (const float*)d_in[11];
    const float* W_out = (const float*)d_in[12];
    const float* b_out = (const float*)d_in[13];

    float* ph;   cudaGetSymbolAddress((void**)&ph,   g_h);
    float* pag;  cudaGetSymbolAddress((void**)&pag,  g_agg);
    float* pz;   cudaGetSymbolAddress((void**)&pz,   g_z);
    float* pwc;  cudaGetSymbolAddress((void**)&pwc,  g_wcat);
    float* pbc;  cudaGetSymbolAddress((void**)&pbc,  g_bcat);
    int* psrow;  cudaGetSymbolAddress((void**)&psrow, g_srow);
    int* pscol;  cudaGetSymbolAddress((void**)&pscol, g_scol);

    auto smem_g3 = [](int kdim) { return (kdim * 64 + 64 + 8 * 64 * 16) * 4; };
    const int sm_ei  = smem_g3(64);
    const int sm_p   = smem_g3(128);
    const int sm_m128 = (64 + 128 * XSTR + 16 * 4 * 32 * 4) * 4;
    const int sm_m192 = (64 + 128 * XSTR + 24 * 4 * 32 * 4) * 4;

    cudaFuncSetAttribute(edge_kernel2, cudaFuncAttributeMaxDynamicSharedMemorySize, SM_EDGE_BYTES);
    cudaFuncSetAttribute(node_mma<128, 128, false>,
                         cudaFuncAttributeMaxDynamicSharedMemorySize, sm_m128);
    cudaFuncSetAttribute(node_mma<192, 128, true>,
                         cudaFuncAttributeMaxDynamicSharedMemorySize, sm_m192);
    cudaFuncSetAttribute(node_gemm3<64, 64, 128, false, false>,
                         cudaFuncAttributeMaxDynamicSharedMemorySize, sm_ei);
    cudaFuncSetAttribute(node_gemm3<128, 128, 128, false, true>,
                         cudaFuncAttributeMaxDynamicSharedMemorySize, sm_p);
    cudaFuncSetAttribute(node_gemm3<128, 128, 64, false, false>,
                         cudaFuncAttributeMaxDynamicSharedMemorySize, sm_p);

    const int EB = (E_EDGES + 255) / 256;

    // sort edges by row + repack all layer-1 edge weights
    k_zero_deg<<<SCAN_BLOCKS, 256>>>();
    k_hist<<<EB, 256>>>(edges);
    k_scan1<<<SCAN_BLOCKS, 256>>>();
    k_scan2<<<1, 256>>>();
    k_scan3<<<SCAN_BLOCKS, 256>>>();
    k_sort_scatter<<<EB, 256>>>(edges);
    k_repack<<<(L_LAYERS * HID * HID + 255) / 256, 256>>>(eW1, eb1);

    // embedding_in (fp32)
    node_gemm3<64, 64, 128, false, false><<<dim3(148, 2), 256, sm_ei>>>(
        h_in, nullptr, W_in, b_in, ph);

    for (int l = 0; l < L_LAYERS; l++) {
        k_zero_agg<<<(N_NODES * EH / 4 + 255) / 256, 256>>>();
        node_mma<128, 128, false><<<dim3(148, 2), 256, sm_m128>>>(
            ph, nullptr, pwc + l * HID * HID, pbc + l * HID, pz);
        edge_kernel2<<<592, 256, SM_EDGE_BYTES>>>(
            psrow, pscol, pz, eW2 + l * EH * EH, eb2 + l * EH);
        node_mma<192, 128, true><<<dim3(148, 2), 256, sm_m192>>>(
            ph, pag, nW1 + l * (HID + EH) * HID, nb1 + l * HID, pz);
        node_gemm3<128, 128, 128, false, true><<<dim3(148, 2), 256, sm_p>>>(
            pz, nullptr, nW2 + l * HID * HID, nb2 + l * HID, ph);
    }

    // embedding_out (fp32)
    node_gemm3<128, 128, 64, false, false><<<dim3(148, 1), 256, sm_p>>>(
        ph, nullptr, W_out, b_out, (float*)d_out);
}

// round 11
// speedup vs baseline: 1.0261x; 1.0261x over previous
#include <cuda_runtime.h>
#include <cuda_bf16.h>
#include <cstdint>

// GNN_84421877170708: 4-layer GCL GNN. Round 11:
//  - revert round-10 occupancy regression (3 CTAs/SM, XSTR 82)
//  - edge kernel made fully warp-autonomous: per-warp 16-edge groups,
//    __syncwarp instead of __syncthreads (dataflow is warp-local).

#define N_NODES 50000
#define E_EDGES 800000
#define IN_NF   64
#define HID     128
#define EH      64
#define OUT_NF  64
#define L_LAYERS 4
#define XSTR    82
#define SCAN_BLOCKS ((N_NODES + 255) / 256)

__device__ float g_h[N_NODES * HID];
__device__ float g_agg[N_NODES * EH];
__device__ float g_z[N_NODES * HID];
__device__ float g_wcat[L_LAYERS * HID * HID];
__device__ float g_bcat[L_LAYERS * HID];

__device__ int g_deg[N_NODES];
__device__ int g_base[N_NODES];
__device__ int g_cursor[N_NODES];
__device__ int g_bsums[256];
__device__ int g_srow[E_EDGES];
__device__ int g_scol[E_EDGES];

using u64 = unsigned long long;
using u32 = unsigned int;

__device__ __forceinline__ float silu(float v) {
    float h = 0.5f * v, t;
    asm("tanh.approx.f32 %0, %1;" : "=f"(t) : "f"(h));
    return fmaf(h, t, h);
}
__device__ __forceinline__ u32 f2tf32(float f) {
    u32 r; asm("cvt.rna.tf32.f32 %0, %1;" : "=r"(r) : "f"(f)); return r;
}
__device__ __forceinline__ float tf32f(float f) {
    return __uint_as_float(f2tf32(f));
}
__device__ __forceinline__ void mma_tf32(float* c, u32 a0, u32 a1, u32 a2, u32 a3,
                                         u32 b0, u32 b1) {
    asm volatile(
        "mma.sync.aligned.m16n8k8.row.col.f32.tf32.tf32.f32 "
        "{%0,%1,%2,%3}, {%4,%5,%6,%7}, {%8,%9}, {%0,%1,%2,%3};"
        : "+f"(c[0]), "+f"(c[1]), "+f"(c[2]), "+f"(c[3])
        : "r"(a0), "r"(a1), "r"(a2), "r"(a3), "r"(b0), "r"(b1));
}
__device__ __forceinline__ void red4(float* p, float a, float b, float c, float d) {
    asm volatile("red.global.add.v4.f32 [%0], {%1,%2,%3,%4};"
                 :: "l"(p), "f"(a), "f"(b), "f"(c), "f"(d) : "memory");
}
__device__ __forceinline__ void ffma2(u64& acc, u64 x, u64 w) {
    asm("fma.rn.f32x2 %0, %1, %2, %0;" : "+l"(acc) : "l"(x), "l"(w));
}
__device__ __forceinline__ u64 pack2(float x) {
    u64 r; asm("mov.b64 %0, {%1, %1};" : "=l"(r) : "f"(x)); return r;
}
__device__ __forceinline__ u64 packf2(float a, float b) {
    u64 r; asm("mov.b64 %0, {%1, %2};" : "=l"(r) : "f"(a), "f"(b)); return r;
}
__device__ __forceinline__ float2 unpack2(u64 v) {
    float2 r; asm("mov.b64 {%0, %1}, %2;" : "=f"(r.x), "=f"(r.y) : "l"(v)); return r;
}

// ---------------------------------------------------------------------------
// counting sort of edges by row
// ---------------------------------------------------------------------------
__global__ void k_zero_deg() {
    int i = blockIdx.x * 256 + threadIdx.x;
    if (i < N_NODES) { g_deg[i] = 0; g_cursor[i] = 0; }
}
__global__ void k_hist(const int* __restrict__ edges) {
    int e = blockIdx.x * 256 + threadIdx.x;
    if (e < E_EDGES) atomicAdd(&g_deg[edges[e]], 1);
}
__global__ void k_scan1() {
    __shared__ int s[256];
    int i = blockIdx.x * 256 + threadIdx.x;
    int v = (i < N_NODES) ? g_deg[i] : 0;
    s[threadIdx.x] = v;
    __syncthreads();
#pragma unroll
    for (int o = 1; o < 256; o <<= 1) {
        int t = (threadIdx.x >= o) ? s[threadIdx.x - o] : 0;
        __syncthreads();
        s[threadIdx.x] += t;
        __syncthreads();
    }
    if (i < N_NODES) g_base[i] = s[threadIdx.x] - v;
    if (threadIdx.x == 255) g_bsums[blockIdx.x] = s[255];
}
__global__ void k_scan2() {
    __shared__ int s[256];
    int i = threadIdx.x;
    int v = (i < SCAN_BLOCKS) ? g_bsums[i] : 0;
    s[i] = v;
    __syncthreads();
#pragma unroll
    for (int o = 1; o < 256; o <<= 1) {
        int t = (i >= o) ? s[i - o] : 0;
        __syncthreads();
        s[i] += t;
        __syncthreads();
    }
    g_bsums[i] = s[i] - v;
}
__global__ void k_scan3() {
    int i = blockIdx.x * 256 + threadIdx.x;
    if (i < N_NODES) g_base[i] += g_bsums[blockIdx.x];
}
__global__ void k_sort_scatter(const int* __restrict__ edges) {
    int e = blockIdx.x * 256 + threadIdx.x;
    if (e < E_EDGES) {
        int r = edges[e], c = edges[E_EDGES + e];
        int pos = g_base[r] + atomicAdd(&g_cursor[r], 1);
        g_srow[pos] = r;
        g_scol[pos] = c;
    }
}

// ---------------------------------------------------------------------------
// repack ALL layers' W1 -> g_wcat[l][128x128], g_bcat[l] = [b1|0]  (once)
// ---------------------------------------------------------------------------
__global__ void k_repack(const float* __restrict__ eW1, const float* __restrict__ eb1) {
    int i = blockIdx.x * 256 + threadIdx.x;
    if (i < L_LAYERS * HID * HID) {
        int l = i >> 14, r = i & 16383;
        int k = r >> 7, j = r & 127;
        const float* w = eW1 + l * 2 * HID * EH;
        g_wcat[i] = (j < 64) ? w[k * 64 + j] : w[(k + 128) * 64 + (j - 64)];
    }
    if (i < L_LAYERS * HID) {
        int l = i >> 7, j = i & 127;
        g_bcat[i] = (j < 64) ? eb1[l * EH + j] : 0.f;
    }
}

__global__ void k_zero_agg() {
    int i = blockIdx.x * 256 + threadIdx.x;
    if (i < N_NODES * EH / 4)
        ((float4*)g_agg)[i] = make_float4(0.f, 0.f, 0.f, 0.f);
}

// ---------------------------------------------------------------------------
// node_mma (tf32): out[:, yoff:+64] = act(concat(in1,in2) @ W[:, yoff:+64] + b)
// ---------------------------------------------------------------------------
template<int KDIM, int W1IN, bool DO_SILU>
__global__ void __launch_bounds__(256, 2) node_mma(
    const float* __restrict__ in1, const float* __restrict__ in2,
    const float* __restrict__ W, const float* __restrict__ b,
    float* __restrict__ out)
{
    constexpr int NSTEP = KDIM / 8;
    extern __shared__ float sm[];
    float* bs = sm;
    float* X  = sm + 64;
    float* Bp = X + 128 * XSTR;

    const int tid  = threadIdx.x;
    const int warp = tid >> 5, lane = tid & 31;
    const int g    = lane >> 2, tig = lane & 3;
    const int yoff = blockIdx.y * 64;

    for (int i = tid; i < NSTEP * 4 * 32; i += 256) {
        int s  = i >> 7;
        int gp = (i >> 5) & 3;
        int ln = i & 31;
        int gg = ln >> 2, tt = ln & 3;
        int k0 = s * 8;
        int nA = yoff + gp * 16 + (gg >> 1) * 4 + (gg & 1);
        int nB = nA + 2;
        float4 v;
        v.x = tf32f(W[(size_t)(k0 + tt)     * HID + nA]);
        v.y = tf32f(W[(size_t)(k0 + tt + 4) * HID + nA]);
        v.z = tf32f(W[(size_t)(k0 + tt)     * HID + nB]);
        v.w = tf32f(W[(size_t)(k0 + tt + 4) * HID + nB]);
        *(float4*)&Bp[i * 4] = v;
    }
    if (tid < 64) bs[tid] = b[yoff + tid];

    const float* xlo = X + (warp * 16 + g) * XSTR + tig * 2;
    const float* xhi = xlo + 8 * XSTR;
    const int e  = tid >> 1;
    const int hf = tid & 1;

    const int NTILES = (N_NODES + 127) / 128;
    for (int t = blockIdx.x; t < NTILES; t += gridDim.x) {
        const int tb = t * 128;
        int node = tb + e;
        if (node >= N_NODES) node = 0;

        float acc[8][4];
#pragma unroll
        for (int a = 0; a < 8; a++)
#pragma unroll
            for (int c = 0; c < 4; c++) acc[a][c] = 0.f;

#pragma unroll
        for (int c0 = 0; c0 < KDIM; c0 += 64) {
            __syncthreads();
            {
                const int kb = c0 + hf * 32;
                const float4* src;
                if (KDIM == W1IN || kb < W1IN)
                    src = (const float4*)(in1 + (size_t)node * W1IN + kb);
                else
                    src = (const float4*)(in2 + (size_t)node * (KDIM - W1IN) + (kb - W1IN));
                float* xr = X + e * XSTR + hf * 32;
#pragma unroll
                for (int bb = 0; bb < 4; bb++) {
                    float4 x0 = src[2 * bb];
                    float4 x1 = src[2 * bb + 1];
                    *(float2*)&xr[bb * 8 + 0] = make_float2(tf32f(x0.x), tf32f(x1.x));
                    *(float2*)&xr[bb * 8 + 2] = make_float2(tf32f(x0.y), tf32f(x1.y));
                    *(float2*)&xr[bb * 8 + 4] = make_float2(tf32f(x0.z), tf32f(x1.z));
                    *(float2*)&xr[bb * 8 + 6] = make_float2(tf32f(x0.w), tf32f(x1.w));
                }
            }
            __syncthreads();

#pragma unroll
            for (int s8 = 0; s8 < 8; s8++) {
                const int s = (c0 >> 3) + s8;
                float2 alo = *(const float2*)(xlo + s8 * 8);
                float2 ahi = *(const float2*)(xhi + s8 * 8);
                u32 a0 = __float_as_uint(alo.x), a1 = __float_as_uint(ahi.x);
                u32 a2 = __float_as_uint(alo.y), a3 = __float_as_uint(ahi.y);
#pragma unroll
                for (int gp = 0; gp < 4; gp++) {
                    float4 bv = *(const float4*)&Bp[((s * 4 + gp) * 32 + lane) * 4];
                    mma_tf32(acc[gp * 2 + 0], a0, a1, a2, a3,
                             __float_as_uint(bv.x), __float_as_uint(bv.y));
                    mma_tf32(acc[gp * 2 + 1], a0, a1, a2, a3,
                             __float_as_uint(bv.z), __float_as_uint(bv.w));
                }
            }
        }

        {
            int r0 = tb + warp * 16 + g;
            int r1 = r0 + 8;
#pragma unroll
            for (int gp = 0; gp < 4; gp++) {
                int c0 = gp * 16 + tig * 4;
                float4 v0 = make_float4(acc[gp*2][0]   + bs[c0],
                                        acc[gp*2][1]   + bs[c0+1],
                                        acc[gp*2+1][0] + bs[c0+2],
                                        acc[gp*2+1][1] + bs[c0+3]);
                float4 v1 = make_float4(acc[gp*2][2]   + bs[c0],
                                        acc[gp*2][3]   + bs[c0+1],
                                        acc[gp*2+1][2] + bs[c0+2],
                                        acc[gp*2+1][3] + bs[c0+3]);
                if (DO_SILU) {
                    v0.x = silu(v0.x); v0.y = silu(v0.y); v0.z = silu(v0.z); v0.w = silu(v0.w);
                    v1.x = silu(v1.x); v1.y = silu(v1.y); v1.z = silu(v1.z); v1.w = silu(v1.w);
                }
                if (r0 < N_NODES) *(float4*)(out + (size_t)r0 * HID + yoff + c0) = v0;
                if (r1 < N_NODES) *(float4*)(out + (size_t)r1 * HID + yoff + c0) = v1;
            }
        }
    }
}

// ---------------------------------------------------------------------------
// node_gemm3 (fp32, residual nb + embeddings)
// ---------------------------------------------------------------------------
template<int KDIM, int W1IN, int NOUT_TOTAL, bool DO_SILU, bool DO_RES>
__global__ void __launch_bounds__(256, 2) node_gemm3(
    const float* __restrict__ in1, const float* __restrict__ in2,
    const float* __restrict__ W, const float* __restrict__ b,
    float* __restrict__ out)
{
    extern __shared__ float fsmem[];
    float* ws = fsmem;
    float* bs = ws + KDIM * 64;
    float* stg = bs + 64;

    const int tid  = threadIdx.x;
    const int warp = tid >> 5;
    const int lane = tid & 31;
    const int yoff = blockIdx.y * 64;

    for (int i = tid * 4; i < KDIM * 64; i += 1024) {
        int k = i >> 6, j = i & 63;
        *(float4*)&ws[i] = *(const float4*)(W + (size_t)k * NOUT_TOTAL + yoff + j);
    }
    if (tid < 64) bs[tid] = b[yoff + tid];
    __syncthreads();

    float* xs = stg + warp * (64 * 16);
    const int p    = lane >> 2;
    const int q    = lane & 3;
    const int m    = lane >> 1;
    const int half = lane & 1;

    u64 biasr[4];
#pragma unroll
    for (int g = 0; g < 4; g++)
        biasr[g] = packf2(bs[p * 8 + 2 * g], bs[p * 8 + 2 * g + 1]);

    const int gw     = blockIdx.x * 8 + warp;
    const int nwarps = gridDim.x * 8;
    const int ntiles = N_NODES / 16;

    for (int t = gw; t < ntiles; t += nwarps) {
        const int node = t * 16 + m;
        const float* s1 = in1 + (size_t)node * W1IN;
        const float* s2 = (KDIM > W1IN) ? in2 + (size_t)node * (KDIM - W1IN) : nullptr;

        u64 acc[4][4];
#pragma unroll
        for (int d = 0; d < 4; d++)
#pragma unroll
            for (int g = 0; g < 4; g++) acc[d][g] = biasr[g];

#pragma unroll
        for (int c0 = 0; c0 < KDIM; c0 += 64) {
            __syncwarp();
#pragma unroll
            for (int i = 0; i < 8; i++) {
                int kk = c0 + half * 32 + i * 4;
                float4 v;
                if (KDIM == W1IN || kk < W1IN) v = *(const float4*)(s1 + kk);
                else                           v = *(const float4*)(s2 + (kk - W1IN));
                int kl = kk - c0;
                xs[(kl + 0) * 16 + m] = v.x;
                xs[(kl + 1) * 16 + m] = v.y;
                xs[(kl + 2) * 16 + m] = v.z;
                xs[(kl + 3) * 16 + m] = v.w;
            }
            __syncwarp();

#pragma unroll 4
            for (int k = 0; k < 64; k++) {
                float4 xv = *(const float4*)&xs[k * 16 + q * 4];
                const ulonglong2* wp = (const ulonglong2*)(ws + (c0 + k) * 64 + p * 8);
                ulonglong2 wa = wp[0];
                ulonglong2 wb = wp[1];
                u64 xp[4] = {pack2(xv.x), pack2(xv.y), pack2(xv.z), pack2(xv.w)};
#pragma unroll
                for (int d = 0; d < 4; d++) {
                    ffma2(acc[d][0], xp[d], wa.x);
                    ffma2(acc[d][1], xp[d], wa.y);
                    ffma2(acc[d][2], xp[d], wb.x);
                    ffma2(acc[d][3], xp[d], wb.y);
                }
            }
        }

#pragma unroll
        for (int d = 0; d < 4; d++) {
            int nn = t * 16 + q * 4 + d;
            float* dst = out + (size_t)nn * NOUT_TOTAL + yoff + p * 8;
#pragma unroll
            for (int g = 0; g < 2; g++) {
                float2 a = unpack2(acc[d][2 * g]);
                float2 c = unpack2(acc[d][2 * g + 1]);
                float4 v = make_float4(a.x, a.y, c.x, c.y);
                if (DO_SILU) {
                    v.x = silu(v.x); v.y = silu(v.y);
                    v.z = silu(v.z); v.w = silu(v.w);
                }
                if (DO_RES) {
                    float4 r = *(const float4*)(dst + g * 4);
                    v.x += r.x; v.y += r.y; v.z += r.z; v.w += r.w;
                }
                *(float4*)(dst + g * 4) = v;
            }
        }
    }
}

// ---------------------------------------------------------------------------
// Edge kernel: fully warp-autonomous 16-edge groups. Sorted edges.
// Per warp: pairwise gather+silu -> m16 tf32 mma -> writeback ->
// segmented reduction -> red4 per run. Only __syncwarp inside the loop.
// SMEM: idxs[128] | b2s[64] | X2[8 warps * 16 * XSTR] | B2p[4096]
// ---------------------------------------------------------------------------
#define SM_B2S  128
#define SM_X2   192
#define SM_B2P  (192 + 128 * XSTR)
#define SM_EDGE_FLOATS (SM_B2P + 8 * 4 * 32 * 4)
#define SM_EDGE_BYTES  (SM_EDGE_FLOATS * 4)

__global__ void __launch_bounds__(256, 3)
edge_kernel2(const int* __restrict__ srow, const int* __restrict__ scol,
             const float* __restrict__ P,
             const float* __restrict__ W2, const float* __restrict__ b2)
{
    extern __shared__ float sm[];
    int*   idxs = (int*)sm;
    float* b2s  = sm + SM_B2S;
    float* X2   = sm + SM_X2;
    float* B2p  = sm + SM_B2P;

    const int tid  = threadIdx.x;
    const int warp = tid >> 5, lane = tid & 31;
    const int g    = lane >> 2, tig = lane & 3;

    for (int i = tid; i < 8 * 4 * 32; i += 256) {
        int s  = i >> 7;
        int gp = (i >> 5) & 3;
        int ln = i & 31;
        int gg = ln >> 2, tt = ln & 3;
        int k0 = s * 8;
        int nA = gp * 16 + (gg >> 1) * 4 + (gg & 1);
        int nB = nA + 2;
        float4 v;
        v.x = tf32f(W2[(k0 + tt)     * 64 + nA]);
        v.y = tf32f(W2[(k0 + tt + 4) * 64 + nA]);
        v.z = tf32f(W2[(k0 + tt)     * 64 + nB]);
        v.w = tf32f(W2[(k0 + tt + 4) * 64 + nB]);
        *(float4*)&B2p[i * 4] = v;
    }
    if (tid < 64) b2s[tid] = b2[tid];
    __syncthreads();   // B2p/b2s ready (only block-wide barrier)

    int*   widx = idxs + warp * 16;
    float* WX   = X2 + warp * 16 * XSTR;
    const float* xlo = WX + g * XSTR + tig * 2;
    const float* xhi = xlo + 8 * XSTR;
    const int qd = lane & 15;      // column quad
    const int sp = lane >> 4;      // strip (2 strips of 8 edges per warp)

    const int NG = E_EDGES / 16;   // 50000 16-edge groups
    const int gw0 = blockIdx.x * 8 + warp;
    const int gstr = gridDim.x * 8;

    for (int gi = gw0; gi < NG; gi += gstr) {
        // ---- pairwise gather + silu -> WX (frag-interleaved tf32) ----
        {
            int e = lane >> 1, half = lane & 1;
            int row  = srow[gi * 16 + e];
            int coln = scol[gi * 16 + e];
            if (half == 0) widx[e] = row;
            const float4* pa = (const float4*)(P + (size_t)row  * HID + half * 32);
            const float4* pb = (const float4*)(P + (size_t)coln * HID + 64 + half * 32);
            float* xr = WX + e * XSTR + half * 32;
#pragma unroll
            for (int bb = 0; bb < 4; bb++) {
                float4 x0 = pa[2 * bb],     y0 = pb[2 * bb];
                float4 x1 = pa[2 * bb + 1], y1 = pb[2 * bb + 1];
                *(float2*)&xr[bb * 8 + 0] = make_float2(tf32f(silu(x0.x + y0.x)),
                                                        tf32f(silu(x1.x + y1.x)));
                *(float2*)&xr[bb * 8 + 2] = make_float2(tf32f(silu(x0.y + y0.y)),
                                                        tf32f(silu(x1.y + y1.y)));
                *(float2*)&xr[bb * 8 + 4] = make_float2(tf32f(silu(x0.z + y0.z)),
                                                        tf32f(silu(x1.z + y1.z)));
                *(float2*)&xr[bb * 8 + 6] = make_float2(tf32f(silu(x0.w + y0.w)),
                                                        tf32f(silu(x1.w + y1.w)));
            }
        }
        __syncwarp();

        // ---- MLP2 MMA: 16 edges x 64 cols ----
        float acc[8][4];
#pragma unroll
        for (int a = 0; a < 8; a++)
#pragma unroll
            for (int c = 0; c < 4; c++) acc[a][c] = 0.f;

#pragma unroll
        for (int s = 0; s < 8; s++) {
            float2 alo = *(const float2*)(xlo + s * 8);
            float2 ahi = *(const float2*)(xhi + s * 8);
            u32 a0 = __float_as_uint(alo.x), a1 = __float_as_uint(ahi.x);
            u32 a2 = __float_as_uint(alo.y), a3 = __float_as_uint(ahi.y);
#pragma unroll
            for (int gp = 0; gp < 4; gp++) {
                float4 bv = *(const float4*)&B2p[((s * 4 + gp) * 32 + lane) * 4];
                mma_tf32(acc[gp * 2 + 0], a0, a1, a2, a3,
                         __float_as_uint(bv.x), __float_as_uint(bv.y));
                mma_tf32(acc[gp * 2 + 1], a0, a1, a2, a3,
                         __float_as_uint(bv.z), __float_as_uint(bv.w));
            }
        }
        __syncwarp();   // MMA reads of WX done; safe to overwrite

        // ---- write silu(D2 + b2) back into WX rows g, g+8 ----
        {
            float* rlo = WX + g * XSTR;
            float* rhi = WX + (g + 8) * XSTR;
#pragma unroll
            for (int gp = 0; gp < 4; gp++) {
                int c0 = gp * 16 + tig * 4;
                *(float2*)&rlo[c0]     = make_float2(silu(acc[gp*2][0]   + b2s[c0]),
                                                     silu(acc[gp*2][1]   + b2s[c0+1]));
                *(float2*)&rlo[c0 + 2] = make_float2(silu(acc[gp*2+1][0] + b2s[c0+2]),
                                                     silu(acc[gp*2+1][1] + b2s[c0+3]));
                *(float2*)&rhi[c0]     = make_float2(silu(acc[gp*2][2]   + b2s[c0]),
                                                     silu(acc[gp*2][3]   + b2s[c0+1]));
                *(float2*)&rhi[c0 + 2] = make_float2(silu(acc[gp*2+1][2] + b2s[c0+2]),
                                                     silu(acc[gp*2+1][3] + b2s[c0+3]));
            }
        }
        __syncwarp();

        // ---- segmented reduction: lane (qd, sp) walks 8 edges x 4 cols ----
        {
            int e0 = sp * 8;
            int cur = widx[e0];
            const float* r = WX + e0 * XSTR + qd * 4;
            float2 a01 = *(const float2*)(r);
            float2 a23 = *(const float2*)(r + 2);
            float s0 = a01.x, s1 = a01.y, s2 = a23.x, s3 = a23.y;
#pragma unroll
            for (int j = 1; j < 8; j++) {
                int rw = widx[e0 + j];
                const float* rr = WX + (e0 + j) * XSTR + qd * 4;
                float2 b01 = *(const float2*)(rr);
                float2 b23 = *(const float2*)(rr + 2);
                if (rw != cur) {
                    red4(g_agg + (size_t)cur * EH + qd * 4, s0, s1, s2, s3);
                    cur = rw;
                    s0 = b01.x; s1 = b01.y; s2 = b23.x; s3 = b23.y;
                } else {
                    s0 += b01.x; s1 += b01.y; s2 += b23.x; s3 += b23.y;
                }
            }
            red4(g_agg + (size_t)cur * EH + qd * 4, s0, s1, s2, s3);
        }
        __syncwarp();   // WX/widx protected before next gather
    }
}

// ---------------------------------------------------------------------------
extern "C" void kernel_launch(void* const* d_in, const int* in_sizes, int n_in,
                              void* d_out, int out_size)
{
    const float* h_in  = (const float*)d_in[0];
    const int*   edges = (const int*)d_in[1];
    const float* W_in  = (const float*)d_in[2];
    const float* b_in  = (const float*)d_in[3];
    const float* eW1   = (const float*)d_in[4];
    const float* eb1   = (const float*)d_in[5];
    const float* eW2   = (const float*)d_in[6];
    const float* eb2   = (const float*)d_in[7];
    const float* nW1   = (const float*)d_in[8];
    const float* nb1   = (const float*)d_in[9];
    const float* nW2   = (const float*)d_in[10];
    const float* nb2   = (const float*)d_in[11];
    const float* W_out = (const float*)d_in[12];
    const float* b_out = (const float*)d_in[13];

    float* ph;   cudaGetSymbolAddress((void**)&ph,   g_h);
    float* pag;  cudaGetSymbolAddress((void**)&pag,  g_agg);
    float* pz;   cudaGetSymbolAddress((void**)&pz,   g_z);
    float* pwc;  cudaGetSymbolAddress((void**)&pwc,  g_wcat);
    float* pbc;  cudaGetSymbolAddress((void**)&pbc,  g_bcat);
    int* psrow;  cudaGetSymbolAddress((void**)&psrow, g_srow);
    int* pscol;  cudaGetSymbolAddress((void**)&pscol, g_scol);

    auto smem_g3 = [](int kdim) { return (kdim * 64 + 64 + 8 * 64 * 16) * 4; };
    const int sm_ei  = smem_g3(64);
    const int sm_p   = smem_g3(128);
    const int sm_m128 = (64 + 128 * XSTR + 16 * 4 * 32 * 4) * 4;
    const int sm_m192 = (64 + 128 * XSTR + 24 * 4 * 32 * 4) * 4;

    cudaFuncSetAttribute(edge_kernel2, cudaFuncAttributeMaxDynamicSharedMemorySize, SM_EDGE_BYTES);
    cudaFuncSetAttribute(node_mma<128, 128, false>,
                         cudaFuncAttributeMaxDynamicSharedMemorySize, sm_m128);
    cudaFuncSetAttribute(node_mma<192, 128, true>,
                         cudaFuncAttributeMaxDynamicSharedMemorySize, sm_m192);
    cudaFuncSetAttribute(node_gemm3<64, 64, 128, false, false>,
                         cudaFuncAttributeMaxDynamicSharedMemorySize, sm_ei);
    cudaFuncSetAttribute(node_gemm3<128, 128, 128, false, true>,
                         cudaFuncAttributeMaxDynamicSharedMemorySize, sm_p);
    cudaFuncSetAttribute(node_gemm3<128, 128, 64, false, false>,
                         cudaFuncAttributeMaxDynamicSharedMemorySize, sm_p);

    const int EB = (E_EDGES + 255) / 256;

    // sort edges by row + repack all layer-1 edge weights (once)
    k_zero_deg<<<SCAN_BLOCKS, 256>>>();
    k_hist<<<EB, 256>>>(edges);
    k_scan1<<<SCAN_BLOCKS, 256>>>();
    k_scan2<<<1, 256>>>();
    k_scan3<<<SCAN_BLOCKS, 256>>>();
    k_sort_scatter<<<EB, 256>>>(edges);
    k_repack<<<(L_LAYERS * HID * HID + 255) / 256, 256>>>(eW1, eb1);

    // embedding_in (fp32)
    node_gemm3<64, 64, 128, false, false><<<dim3(148, 2), 256, sm_ei>>>(
        h_in, nullptr, W_in, b_in, ph);

    for (int l = 0; l < L_LAYERS; l++) {
        k_zero_agg<<<(N_NODES * EH / 4 + 255) / 256, 256>>>();
        node_mma<128, 128, false><<<dim3(148, 2), 256, sm_m128>>>(
            ph, nullptr, pwc + l * HID * HID, pbc + l * HID, pz);
        edge_kernel2<<<444, 256, SM_EDGE_BYTES>>>(
            psrow, pscol, pz, eW2 + l * EH * EH, eb2 + l * EH);
        node_mma<192, 128, true><<<dim3(148, 2), 256, sm_m192>>>(
            ph, pag, nW1 + l * (HID + EH) * HID, nb1 + l * HID, pz);
        node_gemm3<128, 128, 128, false, true><<<dim3(148, 2), 256, sm_p>>>(
            pz, nullptr, nW2 + l * HID * HID, nb2 + l * HID, ph);
    }

    // embedding_out (fp32)
    node_gemm3<128, 128, 64, false, false><<<dim3(148, 1), 256, sm_p>>>(
        ph, nullptr, W_out, b_out, (float*)d_out);
}

// round 12
// speedup vs baseline: 1.1553x; 1.1259x over previous
#include <cuda_runtime.h>
#include <cuda_bf16.h>
#include <cuda_fp16.h>
#include <cstdint>

// GNN_84421877170708: 4-layer GCL GNN. Round 12:
//  - col-half of P mirrored to fp16 (g_ph): random col-gather bytes/wavefronts
//    halved in the edge kernel (the L1tex-bound path).
//  - agg zeroing fused into the P node_mma (4 launches removed).

#define N_NODES 50000
#define E_EDGES 800000
#define IN_NF   64
#define HID     128
#define EH      64
#define OUT_NF  64
#define L_LAYERS 4
#define XSTR    82
#define SCAN_BLOCKS ((N_NODES + 255) / 256)

__device__ float  g_h[N_NODES * HID];
__device__ float  g_agg[N_NODES * EH];
__device__ float  g_z[N_NODES * HID];
__device__ __half g_ph[N_NODES * 64];          // fp16 mirror of P[:,64:128]
__device__ float  g_wcat[L_LAYERS * HID * HID];
__device__ float  g_bcat[L_LAYERS * HID];

__device__ int g_deg[N_NODES];
__device__ int g_base[N_NODES];
__device__ int g_cursor[N_NODES];
__device__ int g_bsums[256];
__device__ int g_srow[E_EDGES];
__device__ int g_scol[E_EDGES];

using u64 = unsigned long long;
using u32 = unsigned int;

__device__ __forceinline__ float silu(float v) {
    float h = 0.5f * v, t;
    asm("tanh.approx.f32 %0, %1;" : "=f"(t) : "f"(h));
    return fmaf(h, t, h);
}
__device__ __forceinline__ u32 f2tf32(float f) {
    u32 r; asm("cvt.rna.tf32.f32 %0, %1;" : "=r"(r) : "f"(f)); return r;
}
__device__ __forceinline__ float tf32f(float f) {
    return __uint_as_float(f2tf32(f));
}
__device__ __forceinline__ void mma_tf32(float* c, u32 a0, u32 a1, u32 a2, u32 a3,
                                         u32 b0, u32 b1) {
    asm volatile(
        "mma.sync.aligned.m16n8k8.row.col.f32.tf32.tf32.f32 "
        "{%0,%1,%2,%3}, {%4,%5,%6,%7}, {%8,%9}, {%0,%1,%2,%3};"
        : "+f"(c[0]), "+f"(c[1]), "+f"(c[2]), "+f"(c[3])
        : "r"(a0), "r"(a1), "r"(a2), "r"(a3), "r"(b0), "r"(b1));
}
__device__ __forceinline__ void red4(float* p, float a, float b, float c, float d) {
    asm volatile("red.global.add.v4.f32 [%0], {%1,%2,%3,%4};"
                 :: "l"(p), "f"(a), "f"(b), "f"(c), "f"(d) : "memory");
}
__device__ __forceinline__ void ffma2(u64& acc, u64 x, u64 w) {
    asm("fma.rn.f32x2 %0, %1, %2, %0;" : "+l"(acc) : "l"(x), "l"(w));
}
__device__ __forceinline__ u64 pack2(float x) {
    u64 r; asm("mov.b64 %0, {%1, %1};" : "=l"(r) : "f"(x)); return r;
}
__device__ __forceinline__ u64 packf2(float a, float b) {
    u64 r; asm("mov.b64 %0, {%1, %2};" : "=l"(r) : "f"(a), "f"(b)); return r;
}
__device__ __forceinline__ float2 unpack2(u64 v) {
    float2 r; asm("mov.b64 {%0, %1}, %2;" : "=f"(r.x), "=f"(r.y) : "l"(v)); return r;
}
__device__ __forceinline__ float2 h2f(u32 h) {
    return __half22float2(*reinterpret_cast<const __half2*>(&h));
}

// ---------------------------------------------------------------------------
// counting sort of edges by row
// ---------------------------------------------------------------------------
__global__ void k_zero_deg() {
    int i = blockIdx.x * 256 + threadIdx.x;
    if (i < N_NODES) { g_deg[i] = 0; g_cursor[i] = 0; }
}
__global__ void k_hist(const int* __restrict__ edges) {
    int e = blockIdx.x * 256 + threadIdx.x;
    if (e < E_EDGES) atomicAdd(&g_deg[edges[e]], 1);
}
__global__ void k_scan1() {
    __shared__ int s[256];
    int i = blockIdx.x * 256 + threadIdx.x;
    int v = (i < N_NODES) ? g_deg[i] : 0;
    s[threadIdx.x] = v;
    __syncthreads();
#pragma unroll
    for (int o = 1; o < 256; o <<= 1) {
        int t = (threadIdx.x >= o) ? s[threadIdx.x - o] : 0;
        __syncthreads();
        s[threadIdx.x] += t;
        __syncthreads();
    }
    if (i < N_NODES) g_base[i] = s[threadIdx.x] - v;
    if (threadIdx.x == 255) g_bsums[blockIdx.x] = s[255];
}
__global__ void k_scan2() {
    __shared__ int s[256];
    int i = threadIdx.x;
    int v = (i < SCAN_BLOCKS) ? g_bsums[i] : 0;
    s[i] = v;
    __syncthreads();
#pragma unroll
    for (int o = 1; o < 256; o <<= 1) {
        int t = (i >= o) ? s[i - o] : 0;
        __syncthreads();
        s[i] += t;
        __syncthreads();
    }
    g_bsums[i] = s[i] - v;
}
__global__ void k_scan3() {
    int i = blockIdx.x * 256 + threadIdx.x;
    if (i < N_NODES) g_base[i] += g_bsums[blockIdx.x];
}
__global__ void k_sort_scatter(const int* __restrict__ edges) {
    int e = blockIdx.x * 256 + threadIdx.x;
    if (e < E_EDGES) {
        int r = edges[e], c = edges[E_EDGES + e];
        int pos = g_base[r] + atomicAdd(&g_cursor[r], 1);
        g_srow[pos] = r;
        g_scol[pos] = c;
    }
}

// ---------------------------------------------------------------------------
// repack ALL layers' W1 -> g_wcat[l][128x128], g_bcat[l] = [b1|0]  (once)
// ---------------------------------------------------------------------------
__global__ void k_repack(const float* __restrict__ eW1, const float* __restrict__ eb1) {
    int i = blockIdx.x * 256 + threadIdx.x;
    if (i < L_LAYERS * HID * HID) {
        int l = i >> 14, r = i & 16383;
        int k = r >> 7, j = r & 127;
        const float* w = eW1 + l * 2 * HID * EH;
        g_wcat[i] = (j < 64) ? w[k * 64 + j] : w[(k + 128) * 64 + (j - 64)];
    }
    if (i < L_LAYERS * HID) {
        int l = i >> 7, j = i & 127;
        g_bcat[i] = (j < 64) ? eb1[l * EH + j] : 0.f;
    }
}

// ---------------------------------------------------------------------------
// node_mma (tf32): out[:, yoff:+64] = act(concat(in1,in2) @ W[:, yoff:+64] + b)
// WRITE_H: yoff==64 CTAs mirror the result to fp16 g_ph.
// ZERO_AGG: yoff==0 CTAs zero their tile's g_agg rows.
// ---------------------------------------------------------------------------
template<int KDIM, int W1IN, bool DO_SILU, bool WRITE_H, bool ZERO_AGG>
__global__ void __launch_bounds__(256, 2) node_mma(
    const float* __restrict__ in1, const float* __restrict__ in2,
    const float* __restrict__ W, const float* __restrict__ b,
    float* __restrict__ out)
{
    constexpr int NSTEP = KDIM / 8;
    extern __shared__ float sm[];
    float* bs = sm;
    float* X  = sm + 64;
    float* Bp = X + 128 * XSTR;

    const int tid  = threadIdx.x;
    const int warp = tid >> 5, lane = tid & 31;
    const int g    = lane >> 2, tig = lane & 3;
    const int yoff = blockIdx.y * 64;

    for (int i = tid; i < NSTEP * 4 * 32; i += 256) {
        int s  = i >> 7;
        int gp = (i >> 5) & 3;
        int ln = i & 31;
        int gg = ln >> 2, tt = ln & 3;
        int k0 = s * 8;
        int nA = yoff + gp * 16 + (gg >> 1) * 4 + (gg & 1);
        int nB = nA + 2;
        float4 v;
        v.x = tf32f(W[(size_t)(k0 + tt)     * HID + nA]);
        v.y = tf32f(W[(size_t)(k0 + tt + 4) * HID + nA]);
        v.z = tf32f(W[(size_t)(k0 + tt)     * HID + nB]);
        v.w = tf32f(W[(size_t)(k0 + tt + 4) * HID + nB]);
        *(float4*)&Bp[i * 4] = v;
    }
    if (tid < 64) bs[tid] = b[yoff + tid];

    const float* xlo = X + (warp * 16 + g) * XSTR + tig * 2;
    const float* xhi = xlo + 8 * XSTR;
    const int e  = tid >> 1;
    const int hf = tid & 1;

    const int NTILES = (N_NODES + 127) / 128;
    for (int t = blockIdx.x; t < NTILES; t += gridDim.x) {
        const int tb = t * 128;
        int node = tb + e;
        if (node >= N_NODES) node = 0;

        if (ZERO_AGG && blockIdx.y == 0) {
            float4* az = (float4*)g_agg;
            int f0 = tb * 16 + tid * 8;
#pragma unroll
            for (int i = 0; i < 8; i++) {
                int f = f0 + i;
                if (f < N_NODES * 16) az[f] = make_float4(0.f, 0.f, 0.f, 0.f);
            }
        }

        float acc[8][4];
#pragma unroll
        for (int a = 0; a < 8; a++)
#pragma unroll
            for (int c = 0; c < 4; c++) acc[a][c] = 0.f;

#pragma unroll
        for (int c0 = 0; c0 < KDIM; c0 += 64) {
            __syncthreads();
            {
                const int kb = c0 + hf * 32;
                const float4* src;
                if (KDIM == W1IN || kb < W1IN)
                    src = (const float4*)(in1 + (size_t)node * W1IN + kb);
                else
                    src = (const float4*)(in2 + (size_t)node * (KDIM - W1IN) + (kb - W1IN));
                float* xr = X + e * XSTR + hf * 32;
#pragma unroll
                for (int bb = 0; bb < 4; bb++) {
                    float4 x0 = src[2 * bb];
                    float4 x1 = src[2 * bb + 1];
                    *(float2*)&xr[bb * 8 + 0] = make_float2(tf32f(x0.x), tf32f(x1.x));
                    *(float2*)&xr[bb * 8 + 2] = make_float2(tf32f(x0.y), tf32f(x1.y));
                    *(float2*)&xr[bb * 8 + 4] = make_float2(tf32f(x0.z), tf32f(x1.z));
                    *(float2*)&xr[bb * 8 + 6] = make_float2(tf32f(x0.w), tf32f(x1.w));
                }
            }
            __syncthreads();

#pragma unroll
            for (int s8 = 0; s8 < 8; s8++) {
                const int s = (c0 >> 3) + s8;
                float2 alo = *(const float2*)(xlo + s8 * 8);
                float2 ahi = *(const float2*)(xhi + s8 * 8);
                u32 a0 = __float_as_uint(alo.x), a1 = __float_as_uint(ahi.x);
                u32 a2 = __float_as_uint(alo.y), a3 = __float_as_uint(ahi.y);
#pragma unroll
                for (int gp = 0; gp < 4; gp++) {
                    float4 bv = *(const float4*)&Bp[((s * 4 + gp) * 32 + lane) * 4];
                    mma_tf32(acc[gp * 2 + 0], a0, a1, a2, a3,
                             __float_as_uint(bv.x), __float_as_uint(bv.y));
                    mma_tf32(acc[gp * 2 + 1], a0, a1, a2, a3,
                             __float_as_uint(bv.z), __float_as_uint(bv.w));
                }
            }
        }

        {
            int r0 = tb + warp * 16 + g;
            int r1 = r0 + 8;
#pragma unroll
            for (int gp = 0; gp < 4; gp++) {
                int c0 = gp * 16 + tig * 4;
                float4 v0 = make_float4(acc[gp*2][0]   + bs[c0],
                                        acc[gp*2][1]   + bs[c0+1],
                                        acc[gp*2+1][0] + bs[c0+2],
                                        acc[gp*2+1][1] + bs[c0+3]);
                float4 v1 = make_float4(acc[gp*2][2]   + bs[c0],
                                        acc[gp*2][3]   + bs[c0+1],
                                        acc[gp*2+1][2] + bs[c0+2],
                                        acc[gp*2+1][3] + bs[c0+3]);
                if (DO_SILU) {
                    v0.x = silu(v0.x); v0.y = silu(v0.y); v0.z = silu(v0.z); v0.w = silu(v0.w);
                    v1.x = silu(v1.x); v1.y = silu(v1.y); v1.z = silu(v1.z); v1.w = silu(v1.w);
                }
                if (r0 < N_NODES) {
                    *(float4*)(out + (size_t)r0 * HID + yoff + c0) = v0;
                    if (WRITE_H && blockIdx.y == 1) {
                        __half2* d = (__half2*)(g_ph + (size_t)r0 * 64 + c0);
                        d[0] = __floats2half2_rn(v0.x, v0.y);
                        d[1] = __floats2half2_rn(v0.z, v0.w);
                    }
                }
                if (r1 < N_NODES) {
                    *(float4*)(out + (size_t)r1 * HID + yoff + c0) = v1;
                    if (WRITE_H && blockIdx.y == 1) {
                        __half2* d = (__half2*)(g_ph + (size_t)r1 * 64 + c0);
                        d[0] = __floats2half2_rn(v1.x, v1.y);
                        d[1] = __floats2half2_rn(v1.z, v1.w);
                    }
                }
            }
        }
    }
}

// ---------------------------------------------------------------------------
// node_gemm3 (fp32, residual nb + embeddings)
// ---------------------------------------------------------------------------
template<int KDIM, int W1IN, int NOUT_TOTAL, bool DO_SILU, bool DO_RES>
__global__ void __launch_bounds__(256, 2) node_gemm3(
    const float* __restrict__ in1, const float* __restrict__ in2,
    const float* __restrict__ W, const float* __restrict__ b,
    float* __restrict__ out)
{
    extern __shared__ float fsmem[];
    float* ws = fsmem;
    float* bs = ws + KDIM * 64;
    float* stg = bs + 64;

    const int tid  = threadIdx.x;
    const int warp = tid >> 5;
    const int lane = tid & 31;
    const int yoff = blockIdx.y * 64;

    for (int i = tid * 4; i < KDIM * 64; i += 1024) {
        int k = i >> 6, j = i & 63;
        *(float4*)&ws[i] = *(const float4*)(W + (size_t)k * NOUT_TOTAL + yoff + j);
    }
    if (tid < 64) bs[tid] = b[yoff + tid];
    __syncthreads();

    float* xs = stg + warp * (64 * 16);
    const int p    = lane >> 2;
    const int q    = lane & 3;
    const int m    = lane >> 1;
    const int half = lane & 1;

    u64 biasr[4];
#pragma unroll
    for (int g = 0; g < 4; g++)
        biasr[g] = packf2(bs[p * 8 + 2 * g], bs[p * 8 + 2 * g + 1]);

    const int gw     = blockIdx.x * 8 + warp;
    const int nwarps = gridDim.x * 8;
    const int ntiles = N_NODES / 16;

    for (int t = gw; t < ntiles; t += nwarps) {
        const int node = t * 16 + m;
        const float* s1 = in1 + (size_t)node * W1IN;
        const float* s2 = (KDIM > W1IN) ? in2 + (size_t)node * (KDIM - W1IN) : nullptr;

        u64 acc[4][4];
#pragma unroll
        for (int d = 0; d < 4; d++)
#pragma unroll
            for (int g = 0; g < 4; g++) acc[d][g] = biasr[g];

#pragma unroll
        for (int c0 = 0; c0 < KDIM; c0 += 64) {
            __syncwarp();
#pragma unroll
            for (int i = 0; i < 8; i++) {
                int kk = c0 + half * 32 + i * 4;
                float4 v;
                if (KDIM == W1IN || kk < W1IN) v = *(const float4*)(s1 + kk);
                else                           v = *(const float4*)(s2 + (kk - W1IN));
                int kl = kk - c0;
                xs[(kl + 0) * 16 + m] = v.x;
                xs[(kl + 1) * 16 + m] = v.y;
                xs[(kl + 2) * 16 + m] = v.z;
                xs[(kl + 3) * 16 + m] = v.w;
            }
            __syncwarp();

#pragma unroll 4
            for (int k = 0; k < 64; k++) {
                float4 xv = *(const float4*)&xs[k * 16 + q * 4];
                const ulonglong2* wp = (const ulonglong2*)(ws + (c0 + k) * 64 + p * 8);
                ulonglong2 wa = wp[0];
                ulonglong2 wb = wp[1];
                u64 xp[4] = {pack2(xv.x), pack2(xv.y), pack2(xv.z), pack2(xv.w)};
#pragma unroll
                for (int d = 0; d < 4; d++) {
                    ffma2(acc[d][0], xp[d], wa.x);
                    ffma2(acc[d][1], xp[d], wa.y);
                    ffma2(acc[d][2], xp[d], wb.x);
                    ffma2(acc[d][3], xp[d], wb.y);
                }
            }
        }

#pragma unroll
        for (int d = 0; d < 4; d++) {
            int nn = t * 16 + q * 4 + d;
            float* dst = out + (size_t)nn * NOUT_TOTAL + yoff + p * 8;
#pragma unroll
            for (int g = 0; g < 2; g++) {
                float2 a = unpack2(acc[d][2 * g]);
                float2 c = unpack2(acc[d][2 * g + 1]);
                float4 v = make_float4(a.x, a.y, c.x, c.y);
                if (DO_SILU) {
                    v.x = silu(v.x); v.y = silu(v.y);
                    v.z = silu(v.z); v.w = silu(v.w);
                }
                if (DO_RES) {
                    float4 r = *(const float4*)(dst + g * 4);
                    v.x += r.x; v.y += r.y; v.z += r.z; v.w += r.w;
                }
                *(float4*)(dst + g * 4) = v;
            }
        }
    }
}

// ---------------------------------------------------------------------------
// Edge kernel: warp-autonomous 16-edge groups; fp32 row gather (sorted) +
// fp16 col gather (random, half the bytes/wavefronts) -> silu -> tf32 mma ->
// writeback -> segmented reduction -> red4 per run.
// ---------------------------------------------------------------------------
#define SM_B2S  128
#define SM_X2   192
#define SM_B2P  (192 + 128 * XSTR)
#define SM_EDGE_FLOATS (SM_B2P + 8 * 4 * 32 * 4)
#define SM_EDGE_BYTES  (SM_EDGE_FLOATS * 4)

__global__ void __launch_bounds__(256, 3)
edge_kernel2(const int* __restrict__ srow, const int* __restrict__ scol,
             const float* __restrict__ P, const __half* __restrict__ Ph,
             const float* __restrict__ W2, const float* __restrict__ b2)
{
    extern __shared__ float sm[];
    int*   idxs = (int*)sm;
    float* b2s  = sm + SM_B2S;
    float* X2   = sm + SM_X2;
    float* B2p  = sm + SM_B2P;

    const int tid  = threadIdx.x;
    const int warp = tid >> 5, lane = tid & 31;
    const int g    = lane >> 2, tig = lane & 3;

    for (int i = tid; i < 8 * 4 * 32; i += 256) {
        int s  = i >> 7;
        int gp = (i >> 5) & 3;
        int ln = i & 31;
        int gg = ln >> 2, tt = ln & 3;
        int k0 = s * 8;
        int nA = gp * 16 + (gg >> 1) * 4 + (gg & 1);
        int nB = nA + 2;
        float4 v;
        v.x = tf32f(W2[(k0 + tt)     * 64 + nA]);
        v.y = tf32f(W2[(k0 + tt + 4) * 64 + nA]);
        v.z = tf32f(W2[(k0 + tt)     * 64 + nB]);
        v.w = tf32f(W2[(k0 + tt + 4) * 64 + nB]);
        *(float4*)&B2p[i * 4] = v;
    }
    if (tid < 64) b2s[tid] = b2[tid];
    __syncthreads();

    int*   widx = idxs + warp * 16;
    float* WX   = X2 + warp * 16 * XSTR;
    const float* xlo = WX + g * XSTR + tig * 2;
    const float* xhi = xlo + 8 * XSTR;
    const int qd = lane & 15;
    const int sp = lane >> 4;

    const int NG = E_EDGES / 16;
    const int gw0 = blockIdx.x * 8 + warp;
    const int gstr = gridDim.x * 8;

    for (int gi = gw0; gi < NG; gi += gstr) {
        // ---- gather: fp32 row half + fp16 col half; silu; frag-interleave ----
        {
            int e = lane >> 1, half = lane & 1;
            int row  = srow[gi * 16 + e];
            int coln = scol[gi * 16 + e];
            if (half == 0) widx[e] = row;
            const float4* pa = (const float4*)(P + (size_t)row * HID + half * 32);
            const uint4*  pc = (const uint4*)(Ph + (size_t)coln * 64 + half * 32);
            float* xr = WX + e * XSTR + half * 32;
#pragma unroll
            for (int bb = 0; bb < 4; bb++) {
                float4 x0 = pa[2 * bb];
                float4 x1 = pa[2 * bb + 1];
                uint4  hh = pc[bb];                 // 8 fp16 col values jj=8bb..+7
                float2 c01 = h2f(hh.x);
                float2 c23 = h2f(hh.y);
                float2 c45 = h2f(hh.z);
                float2 c67 = h2f(hh.w);
                *(float2*)&xr[bb * 8 + 0] = make_float2(tf32f(silu(x0.x + c01.x)),
                                                        tf32f(silu(x1.x + c45.x)));
                *(float2*)&xr[bb * 8 + 2] = make_float2(tf32f(silu(x0.y + c01.y)),
                                                        tf32f(silu(x1.y + c45.y)));
                *(float2*)&xr[bb * 8 + 4] = make_float2(tf32f(silu(x0.z + c23.x)),
                                                        tf32f(silu(x1.z + c67.x)));
                *(float2*)&xr[bb * 8 + 6] = make_float2(tf32f(silu(x0.w + c23.y)),
                                                        tf32f(silu(x1.w + c67.y)));
            }
        }
        __syncwarp();

        // ---- MLP2 MMA ----
        float acc[8][4];
#pragma unroll
        for (int a = 0; a < 8; a++)
#pragma unroll
            for (int c = 0; c < 4; c++) acc[a][c] = 0.f;

#pragma unroll
        for (int s = 0; s < 8; s++) {
            float2 alo = *(const float2*)(xlo + s * 8);
            float2 ahi = *(const float2*)(xhi + s * 8);
            u32 a0 = __float_as_uint(alo.x), a1 = __float_as_uint(ahi.x);
            u32 a2 = __float_as_uint(alo.y), a3 = __float_as_uint(ahi.y);
#pragma unroll
            for (int gp = 0; gp < 4; gp++) {
                float4 bv = *(const float4*)&B2p[((s * 4 + gp) * 32 + lane) * 4];
                mma_tf32(acc[gp * 2 + 0], a0, a1, a2, a3,
                         __float_as_uint(bv.x), __float_as_uint(bv.y));
                mma_tf32(acc[gp * 2 + 1], a0, a1, a2, a3,
                         __float_as_uint(bv.z), __float_as_uint(bv.w));
            }
        }
        __syncwarp();

        // ---- write silu(D2 + b2) back into WX rows g, g+8 ----
        {
            float* rlo = WX + g * XSTR;
            float* rhi = WX + (g + 8) * XSTR;
#pragma unroll
            for (int gp = 0; gp < 4; gp++) {
                int c0 = gp * 16 + tig * 4;
                *(float2*)&rlo[c0]     = make_float2(silu(acc[gp*2][0]   + b2s[c0]),
                                                     silu(acc[gp*2][1]   + b2s[c0+1]));
                *(float2*)&rlo[c0 + 2] = make_float2(silu(acc[gp*2+1][0] + b2s[c0+2]),
                                                     silu(acc[gp*2+1][1] + b2s[c0+3]));
                *(float2*)&rhi[c0]     = make_float2(silu(acc[gp*2][2]   + b2s[c0]),
                                                     silu(acc[gp*2][3]   + b2s[c0+1]));
                *(float2*)&rhi[c0 + 2] = make_float2(silu(acc[gp*2+1][2] + b2s[c0+2]),
                                                     silu(acc[gp*2+1][3] + b2s[c0+3]));
            }
        }
        __syncwarp();

        // ---- segmented reduction: lane (qd, sp) walks 8 edges x 4 cols ----
        {
            int e0 = sp * 8;
            int cur = widx[e0];
            const float* r = WX + e0 * XSTR + qd * 4;
            float2 a01 = *(const float2*)(r);
            float2 a23 = *(const float2*)(r + 2);
            float s0 = a01.x, s1 = a01.y, s2 = a23.x, s3 = a23.y;
#pragma unroll
            for (int j = 1; j < 8; j++) {
                int rw = widx[e0 + j];
                const float* rr = WX + (e0 + j) * XSTR + qd * 4;
                float2 b01 = *(const float2*)(rr);
                float2 b23 = *(const float2*)(rr + 2);
                if (rw != cur) {
                    red4(g_agg + (size_t)cur * EH + qd * 4, s0, s1, s2, s3);
                    cur = rw;
                    s0 = b01.x; s1 = b01.y; s2 = b23.x; s3 = b23.y;
                } else {
                    s0 += b01.x; s1 += b01.y; s2 += b23.x; s3 += b23.y;
                }
            }
            red4(g_agg + (size_t)cur * EH + qd * 4, s0, s1, s2, s3);
        }
        __syncwarp();
    }
}

// ---------------------------------------------------------------------------
extern "C" void kernel_launch(void* const* d_in, const int* in_sizes, int n_in,
                              void* d_out, int out_size)
{
    const float* h_in  = (const float*)d_in[0];
    const int*   edges = (const int*)d_in[1];
    const float* W_in  = (const float*)d_in[2];
    const float* b_in  = (const float*)d_in[3];
    const float* eW1   = (const float*)d_in[4];
    const float* eb1   = (const float*)d_in[5];
    const float* eW2   = (const float*)d_in[6];
    const float* eb2   = (const float*)d_in[7];
    const float* nW1   = (const float*)d_in[8];
    const float* nb1   = (const float*)d_in[9];
    const float* nW2   = (const float*)d_in[10];
    const float* nb2   = (const float*)d_in[11];
    const float* W_out = (const float*)d_in[12];
    const float* b_out = (const float*)d_in[13];

    float*  ph;   cudaGetSymbolAddress((void**)&ph,   g_h);
    float*  pag;  cudaGetSymbolAddress((void**)&pag,  g_agg);
    float*  pz;   cudaGetSymbolAddress((void**)&pz,   g_z);
    __half* pph;  cudaGetSymbolAddress((void**)&pph,  g_ph);
    float*  pwc;  cudaGetSymbolAddress((void**)&pwc,  g_wcat);
    float*  pbc;  cudaGetSymbolAddress((void**)&pbc,  g_bcat);
    int* psrow;   cudaGetSymbolAddress((void**)&psrow, g_srow);
    int* pscol;   cudaGetSymbolAddress((void**)&pscol, g_scol);

    auto smem_g3 = [](int kdim) { return (kdim * 64 + 64 + 8 * 64 * 16) * 4; };
    const int sm_ei  = smem_g3(64);
    const int sm_p   = smem_g3(128);
    const int sm_m128 = (64 + 128 * XSTR + 16 * 4 * 32 * 4) * 4;
    const int sm_m192 = (64 + 128 * XSTR + 24 * 4 * 32 * 4) * 4;

    cudaFuncSetAttribute(edge_kernel2, cudaFuncAttributeMaxDynamicSharedMemorySize, SM_EDGE_BYTES);
    cudaFuncSetAttribute(node_mma<128, 128, false, true, true>,
                         cudaFuncAttributeMaxDynamicSharedMemorySize, sm_m128);
    cudaFuncSetAttribute(node_mma<192, 128, true, false, false>,
                         cudaFuncAttributeMaxDynamicSharedMemorySize, sm_m192);
    cudaFuncSetAttribute(node_gemm3<64, 64, 128, false, false>,
                         cudaFuncAttributeMaxDynamicSharedMemorySize, sm_ei);
    cudaFuncSetAttribute(node_gemm3<128, 128, 128, false, true>,
                         cudaFuncAttributeMaxDynamicSharedMemorySize, sm_p);
    cudaFuncSetAttribute(node_gemm3<128, 128, 64, false, false>,
                         cudaFuncAttributeMaxDynamicSharedMemorySize, sm_p);

    const int EB = (E_EDGES + 255) / 256;

    // sort edges by row + repack all layer-1 edge weights (once)
    k_zero_deg<<<SCAN_BLOCKS, 256>>>();
    k_hist<<<EB, 256>>>(edges);
    k_scan1<<<SCAN_BLOCKS, 256>>>();
    k_scan2<<<1, 256>>>();
    k_scan3<<<SCAN_BLOCKS, 256>>>();
    k_sort_scatter<<<EB, 256>>>(edges);
    k_repack<<<(L_LAYERS * HID * HID + 255) / 256, 256>>>(eW1, eb1);

    // embedding_in (fp32)
    node_gemm3<64, 64, 128, false, false><<<dim3(148, 2), 256, sm_ei>>>(
        h_in, nullptr, W_in, b_in, ph);

    for (int l = 0; l < L_LAYERS; l++) {
        // P = h @ [W1a|W1b] + [b1|0]  (tf32 mma; also zeroes agg, mirrors fp16)
        node_mma<128, 128, false, true, true><<<dim3(148, 2), 256, sm_m128>>>(
            ph, nullptr, pwc + l * HID * HID, pbc + l * HID, pz);
        edge_kernel2<<<444, 256, SM_EDGE_BYTES>>>(
            psrow, pscol, pz, pph, eW2 + l * EH * EH, eb2 + l * EH);
        // z = silu(concat(h, agg) @ nW1 + nb1)  (tf32 mma)
        node_mma<192, 128, true, false, false><<<dim3(148, 2), 256, sm_m192>>>(
            ph, pag, nW1 + l * (HID + EH) * HID, nb1 + l * HID, pz);
        // h = h + (z @ nW2 + nb2)  (fp32, residual anchor)
        node_gemm3<128, 128, 128, false, true><<<dim3(148, 2), 256, sm_p>>>(
            pz, nullptr, nW2 + l * HID * HID, nb2 + l * HID, ph);
    }

    // embedding_out (fp32)
    node_gemm3<128, 128, 64, false, false><<<dim3(148, 1), 256, sm_p>>>(
        ph, nullptr, W_out, b_out, (float*)d_out);
}

// round 13
// speedup vs baseline: 1.2899x; 1.1165x over previous
#include <cuda_runtime.h>
#include <cuda_bf16.h>
#include <cuda_fp16.h>
#include <cstdint>

// GNN_84421877170708: 4-layer GCL GNN. Round 13:
//  - edge gather fully fp16 (g_phx mirror of P); P-GEMM writes fp16 only
//  - nb (residual GEMM) -> tf32 node_mma with fp32 residual epilogue

#define N_NODES 50000
#define E_EDGES 800000
#define IN_NF   64
#define HID     128
#define EH      64
#define OUT_NF  64
#define L_LAYERS 4
#define XSTR    82
#define SCAN_BLOCKS ((N_NODES + 255) / 256)

__device__ float  g_h[N_NODES * HID];
__device__ float  g_agg[N_NODES * EH];
__device__ float  g_z[N_NODES * HID];
__device__ __half g_phx[N_NODES * HID];        // fp16 mirror of P
__device__ float  g_wcat[L_LAYERS * HID * HID];
__device__ float  g_bcat[L_LAYERS * HID];

__device__ int g_deg[N_NODES];
__device__ int g_base[N_NODES];
__device__ int g_cursor[N_NODES];
__device__ int g_bsums[256];
__device__ int g_srow[E_EDGES];
__device__ int g_scol[E_EDGES];

using u64 = unsigned long long;
using u32 = unsigned int;

__device__ __forceinline__ float silu(float v) {
    float h = 0.5f * v, t;
    asm("tanh.approx.f32 %0, %1;" : "=f"(t) : "f"(h));
    return fmaf(h, t, h);
}
__device__ __forceinline__ u32 f2tf32(float f) {
    u32 r; asm("cvt.rna.tf32.f32 %0, %1;" : "=r"(r) : "f"(f)); return r;
}
__device__ __forceinline__ float tf32f(float f) {
    return __uint_as_float(f2tf32(f));
}
__device__ __forceinline__ void mma_tf32(float* c, u32 a0, u32 a1, u32 a2, u32 a3,
                                         u32 b0, u32 b1) {
    asm volatile(
        "mma.sync.aligned.m16n8k8.row.col.f32.tf32.tf32.f32 "
        "{%0,%1,%2,%3}, {%4,%5,%6,%7}, {%8,%9}, {%0,%1,%2,%3};"
        : "+f"(c[0]), "+f"(c[1]), "+f"(c[2]), "+f"(c[3])
        : "r"(a0), "r"(a1), "r"(a2), "r"(a3), "r"(b0), "r"(b1));
}
__device__ __forceinline__ void red4(float* p, float a, float b, float c, float d) {
    asm volatile("red.global.add.v4.f32 [%0], {%1,%2,%3,%4};"
                 :: "l"(p), "f"(a), "f"(b), "f"(c), "f"(d) : "memory");
}
__device__ __forceinline__ void ffma2(u64& acc, u64 x, u64 w) {
    asm("fma.rn.f32x2 %0, %1, %2, %0;" : "+l"(acc) : "l"(x), "l"(w));
}
__device__ __forceinline__ u64 pack2(float x) {
    u64 r; asm("mov.b64 %0, {%1, %1};" : "=l"(r) : "f"(x)); return r;
}
__device__ __forceinline__ u64 packf2(float a, float b) {
    u64 r; asm("mov.b64 %0, {%1, %2};" : "=l"(r) : "f"(a), "f"(b)); return r;
}
__device__ __forceinline__ float2 unpack2(u64 v) {
    float2 r; asm("mov.b64 {%0, %1}, %2;" : "=f"(r.x), "=f"(r.y) : "l"(v)); return r;
}
__device__ __forceinline__ float2 h2f(u32 h) {
    return __half22float2(*reinterpret_cast<const __half2*>(&h));
}

// ---------------------------------------------------------------------------
// counting sort of edges by row
// ---------------------------------------------------------------------------
__global__ void k_zero_deg() {
    int i = blockIdx.x * 256 + threadIdx.x;
    if (i < N_NODES) { g_deg[i] = 0; g_cursor[i] = 0; }
}
__global__ void k_hist(const int* __restrict__ edges) {
    int e = blockIdx.x * 256 + threadIdx.x;
    if (e < E_EDGES) atomicAdd(&g_deg[edges[e]], 1);
}
__global__ void k_scan1() {
    __shared__ int s[256];
    int i = blockIdx.x * 256 + threadIdx.x;
    int v = (i < N_NODES) ? g_deg[i] : 0;
    s[threadIdx.x] = v;
    __syncthreads();
#pragma unroll
    for (int o = 1; o < 256; o <<= 1) {
        int t = (threadIdx.x >= o) ? s[threadIdx.x - o] : 0;
        __syncthreads();
        s[threadIdx.x] += t;
        __syncthreads();
    }
    if (i < N_NODES) g_base[i] = s[threadIdx.x] - v;
    if (threadIdx.x == 255) g_bsums[blockIdx.x] = s[255];
}
__global__ void k_scan2() {
    __shared__ int s[256];
    int i = threadIdx.x;
    int v = (i < SCAN_BLOCKS) ? g_bsums[i] : 0;
    s[i] = v;
    __syncthreads();
#pragma unroll
    for (int o = 1; o < 256; o <<= 1) {
        int t = (i >= o) ? s[i - o] : 0;
        __syncthreads();
        s[i] += t;
        __syncthreads();
    }
    g_bsums[i] = s[i] - v;
}
__global__ void k_scan3() {
    int i = blockIdx.x * 256 + threadIdx.x;
    if (i < N_NODES) g_base[i] += g_bsums[blockIdx.x];
}
__global__ void k_sort_scatter(const int* __restrict__ edges) {
    int e = blockIdx.x * 256 + threadIdx.x;
    if (e < E_EDGES) {
        int r = edges[e], c = edges[E_EDGES + e];
        int pos = g_base[r] + atomicAdd(&g_cursor[r], 1);
        g_srow[pos] = r;
        g_scol[pos] = c;
    }
}

// ---------------------------------------------------------------------------
// repack ALL layers' W1 -> g_wcat[l][128x128], g_bcat[l] = [b1|0]  (once)
// ---------------------------------------------------------------------------
__global__ void k_repack(const float* __restrict__ eW1, const float* __restrict__ eb1) {
    int i = blockIdx.x * 256 + threadIdx.x;
    if (i < L_LAYERS * HID * HID) {
        int l = i >> 14, r = i & 16383;
        int k = r >> 7, j = r & 127;
        const float* w = eW1 + l * 2 * HID * EH;
        g_wcat[i] = (j < 64) ? w[k * 64 + j] : w[(k + 128) * 64 + (j - 64)];
    }
    if (i < L_LAYERS * HID) {
        int l = i >> 7, j = i & 127;
        g_bcat[i] = (j < 64) ? eb1[l * EH + j] : 0.f;
    }
}

// ---------------------------------------------------------------------------
// node_mma (tf32): res = act(concat(in1,in2) @ W[:, yoff:+64] + b)
//   SKIP_OUT: don't write fp32 out; WRITE_H: write fp16 mirror to g_phx;
//   DO_RES: out += res; ZERO_AGG: yoff==0 CTAs zero their tile's g_agg rows.
// ---------------------------------------------------------------------------
template<int KDIM, int W1IN, bool DO_SILU, bool DO_RES, bool WRITE_H, bool SKIP_OUT, bool ZERO_AGG>
__global__ void __launch_bounds__(256, 2) node_mma(
    const float* __restrict__ in1, const float* __restrict__ in2,
    const float* __restrict__ W, const float* __restrict__ b,
    float* __restrict__ out)
{
    constexpr int NSTEP = KDIM / 8;
    extern __shared__ float sm[];
    float* bs = sm;
    float* X  = sm + 64;
    float* Bp = X + 128 * XSTR;

    const int tid  = threadIdx.x;
    const int warp = tid >> 5, lane = tid & 31;
    const int g    = lane >> 2, tig = lane & 3;
    const int yoff = blockIdx.y * 64;

    for (int i = tid; i < NSTEP * 4 * 32; i += 256) {
        int s  = i >> 7;
        int gp = (i >> 5) & 3;
        int ln = i & 31;
        int gg = ln >> 2, tt = ln & 3;
        int k0 = s * 8;
        int nA = yoff + gp * 16 + (gg >> 1) * 4 + (gg & 1);
        int nB = nA + 2;
        float4 v;
        v.x = tf32f(W[(size_t)(k0 + tt)     * HID + nA]);
        v.y = tf32f(W[(size_t)(k0 + tt + 4) * HID + nA]);
        v.z = tf32f(W[(size_t)(k0 + tt)     * HID + nB]);
        v.w = tf32f(W[(size_t)(k0 + tt + 4) * HID + nB]);
        *(float4*)&Bp[i * 4] = v;
    }
    if (tid < 64) bs[tid] = b[yoff + tid];

    const float* xlo = X + (warp * 16 + g) * XSTR + tig * 2;
    const float* xhi = xlo + 8 * XSTR;
    const int e  = tid >> 1;
    const int hf = tid & 1;

    const int NTILES = (N_NODES + 127) / 128;
    for (int t = blockIdx.x; t < NTILES; t += gridDim.x) {
        const int tb = t * 128;
        int node = tb + e;
        if (node >= N_NODES) node = 0;

        if (ZERO_AGG && blockIdx.y == 0) {
            float4* az = (float4*)g_agg;
            int f0 = tb * 16 + tid * 8;
#pragma unroll
            for (int i = 0; i < 8; i++) {
                int f = f0 + i;
                if (f < N_NODES * 16) az[f] = make_float4(0.f, 0.f, 0.f, 0.f);
            }
        }

        float acc[8][4];
#pragma unroll
        for (int a = 0; a < 8; a++)
#pragma unroll
            for (int c = 0; c < 4; c++) acc[a][c] = 0.f;

#pragma unroll
        for (int c0 = 0; c0 < KDIM; c0 += 64) {
            __syncthreads();
            {
                const int kb = c0 + hf * 32;
                const float4* src;
                if (KDIM == W1IN || kb < W1IN)
                    src = (const float4*)(in1 + (size_t)node * W1IN + kb);
                else
                    src = (const float4*)(in2 + (size_t)node * (KDIM - W1IN) + (kb - W1IN));
                float* xr = X + e * XSTR + hf * 32;
#pragma unroll
                for (int bb = 0; bb < 4; bb++) {
                    float4 x0 = src[2 * bb];
                    float4 x1 = src[2 * bb + 1];
                    *(float2*)&xr[bb * 8 + 0] = make_float2(tf32f(x0.x), tf32f(x1.x));
                    *(float2*)&xr[bb * 8 + 2] = make_float2(tf32f(x0.y), tf32f(x1.y));
                    *(float2*)&xr[bb * 8 + 4] = make_float2(tf32f(x0.z), tf32f(x1.z));
                    *(float2*)&xr[bb * 8 + 6] = make_float2(tf32f(x0.w), tf32f(x1.w));
                }
            }
            __syncthreads();

#pragma unroll
            for (int s8 = 0; s8 < 8; s8++) {
                const int s = (c0 >> 3) + s8;
                float2 alo = *(const float2*)(xlo + s8 * 8);
                float2 ahi = *(const float2*)(xhi + s8 * 8);
                u32 a0 = __float_as_uint(alo.x), a1 = __float_as_uint(ahi.x);
                u32 a2 = __float_as_uint(alo.y), a3 = __float_as_uint(ahi.y);
#pragma unroll
                for (int gp = 0; gp < 4; gp++) {
                    float4 bv = *(const float4*)&Bp[((s * 4 + gp) * 32 + lane) * 4];
                    mma_tf32(acc[gp * 2 + 0], a0, a1, a2, a3,
                             __float_as_uint(bv.x), __float_as_uint(bv.y));
                    mma_tf32(acc[gp * 2 + 1], a0, a1, a2, a3,
                             __float_as_uint(bv.z), __float_as_uint(bv.w));
                }
            }
        }

        {
            int r0 = tb + warp * 16 + g;
            int r1 = r0 + 8;
#pragma unroll
            for (int gp = 0; gp < 4; gp++) {
                int c0 = gp * 16 + tig * 4;
                float4 v0 = make_float4(acc[gp*2][0]   + bs[c0],
                                        acc[gp*2][1]   + bs[c0+1],
                                        acc[gp*2+1][0] + bs[c0+2],
                                        acc[gp*2+1][1] + bs[c0+3]);
                float4 v1 = make_float4(acc[gp*2][2]   + bs[c0],
                                        acc[gp*2][3]   + bs[c0+1],
                                        acc[gp*2+1][2] + bs[c0+2],
                                        acc[gp*2+1][3] + bs[c0+3]);
                if (DO_SILU) {
                    v0.x = silu(v0.x); v0.y = silu(v0.y); v0.z = silu(v0.z); v0.w = silu(v0.w);
                    v1.x = silu(v1.x); v1.y = silu(v1.y); v1.z = silu(v1.z); v1.w = silu(v1.w);
                }
                if (r0 < N_NODES) {
                    if (!SKIP_OUT) {
                        float* dst = out + (size_t)r0 * HID + yoff + c0;
                        if (DO_RES) {
                            float4 r = *(const float4*)dst;
                            v0.x += r.x; v0.y += r.y; v0.z += r.z; v0.w += r.w;
                        }
                        *(float4*)dst = v0;
                    }
                    if (WRITE_H) {
                        __half2* d = (__half2*)(g_phx + (size_t)r0 * HID + yoff + c0);
                        d[0] = __floats2half2_rn(v0.x, v0.y);
                        d[1] = __floats2half2_rn(v0.z, v0.w);
                    }
                }
                if (r1 < N_NODES) {
                    if (!SKIP_OUT) {
                        float* dst = out + (size_t)r1 * HID + yoff + c0;
                        if (DO_RES) {
                            float4 r = *(const float4*)dst;
                            v1.x += r.x; v1.y += r.y; v1.z += r.z; v1.w += r.w;
                        }
                        *(float4*)dst = v1;
                    }
                    if (WRITE_H) {
                        __half2* d = (__half2*)(g_phx + (size_t)r1 * HID + yoff + c0);
                        d[0] = __floats2half2_rn(v1.x, v1.y);
                        d[1] = __floats2half2_rn(v1.z, v1.w);
                    }
                }
            }
        }
    }
}

// ---------------------------------------------------------------------------
// node_gemm3 (fp32, embeddings only)
// ---------------------------------------------------------------------------
template<int KDIM, int W1IN, int NOUT_TOTAL, bool DO_SILU, bool DO_RES>
__global__ void __launch_bounds__(256, 2) node_gemm3(
    const float* __restrict__ in1, const float* __restrict__ in2,
    const float* __restrict__ W, const float* __restrict__ b,
    float* __restrict__ out)
{
    extern __shared__ float fsmem[];
    float* ws = fsmem;
    float* bs = ws + KDIM * 64;
    float* stg = bs + 64;

    const int tid  = threadIdx.x;
    const int warp = tid >> 5;
    const int lane = tid & 31;
    const int yoff = blockIdx.y * 64;

    for (int i = tid * 4; i < KDIM * 64; i += 1024) {
        int k = i >> 6, j = i & 63;
        *(float4*)&ws[i] = *(const float4*)(W + (size_t)k * NOUT_TOTAL + yoff + j);
    }
    if (tid < 64) bs[tid] = b[yoff + tid];
    __syncthreads();

    float* xs = stg + warp * (64 * 16);
    const int p    = lane >> 2;
    const int q    = lane & 3;
    const int m    = lane >> 1;
    const int half = lane & 1;

    u64 biasr[4];
#pragma unroll
    for (int g = 0; g < 4; g++)
        biasr[g] = packf2(bs[p * 8 + 2 * g], bs[p * 8 + 2 * g + 1]);

    const int gw     = blockIdx.x * 8 + warp;
    const int nwarps = gridDim.x * 8;
    const int ntiles = N_NODES / 16;

    for (int t = gw; t < ntiles; t += nwarps) {
        const int node = t * 16 + m;
        const float* s1 = in1 + (size_t)node * W1IN;
        const float* s2 = (KDIM > W1IN) ? in2 + (size_t)node * (KDIM - W1IN) : nullptr;

        u64 acc[4][4];
#pragma unroll
        for (int d = 0; d < 4; d++)
#pragma unroll
            for (int g = 0; g < 4; g++) acc[d][g] = biasr[g];

#pragma unroll
        for (int c0 = 0; c0 < KDIM; c0 += 64) {
            __syncwarp();
#pragma unroll
            for (int i = 0; i < 8; i++) {
                int kk = c0 + half * 32 + i * 4;
                float4 v;
                if (KDIM == W1IN || kk < W1IN) v = *(const float4*)(s1 + kk);
                else                           v = *(const float4*)(s2 + (kk - W1IN));
                int kl = kk - c0;
                xs[(kl + 0) * 16 + m] = v.x;
                xs[(kl + 1) * 16 + m] = v.y;
                xs[(kl + 2) * 16 + m] = v.z;
                xs[(kl + 3) * 16 + m] = v.w;
            }
            __syncwarp();

#pragma unroll 4
            for (int k = 0; k < 64; k++) {
                float4 xv = *(const float4*)&xs[k * 16 + q * 4];
                const ulonglong2* wp = (const ulonglong2*)(ws + (c0 + k) * 64 + p * 8);
                ulonglong2 wa = wp[0];
                ulonglong2 wb = wp[1];
                u64 xp[4] = {pack2(xv.x), pack2(xv.y), pack2(xv.z), pack2(xv.w)};
#pragma unroll
                for (int d = 0; d < 4; d++) {
                    ffma2(acc[d][0], xp[d], wa.x);
                    ffma2(acc[d][1], xp[d], wa.y);
                    ffma2(acc[d][2], xp[d], wb.x);
                    ffma2(acc[d][3], xp[d], wb.y);
                }
            }
        }

#pragma unroll
        for (int d = 0; d < 4; d++) {
            int nn = t * 16 + q * 4 + d;
            float* dst = out + (size_t)nn * NOUT_TOTAL + yoff + p * 8;
#pragma unroll
            for (int g = 0; g < 2; g++) {
                float2 a = unpack2(acc[d][2 * g]);
                float2 c = unpack2(acc[d][2 * g + 1]);
                float4 v = make_float4(a.x, a.y, c.x, c.y);
                if (DO_SILU) {
                    v.x = silu(v.x); v.y = silu(v.y);
                    v.z = silu(v.z); v.w = silu(v.w);
                }
                if (DO_RES) {
                    float4 r = *(const float4*)(dst + g * 4);
                    v.x += r.x; v.y += r.y; v.z += r.z; v.w += r.w;
                }
                *(float4*)(dst + g * 4) = v;
            }
        }
    }
}

// ---------------------------------------------------------------------------
// Edge kernel: warp-autonomous 16-edge groups; full fp16 gather (g_phx) ->
// silu -> tf32 mma -> writeback -> segmented reduction -> red4 per run.
// ---------------------------------------------------------------------------
#define SM_B2S  128
#define SM_X2   192
#define SM_B2P  (192 + 128 * XSTR)
#define SM_EDGE_FLOATS (SM_B2P + 8 * 4 * 32 * 4)
#define SM_EDGE_BYTES  (SM_EDGE_FLOATS * 4)

__global__ void __launch_bounds__(256, 3)
edge_kernel2(const int* __restrict__ srow, const int* __restrict__ scol,
             const __half* __restrict__ Phx,
             const float* __restrict__ W2, const float* __restrict__ b2)
{
    extern __shared__ float sm[];
    int*   idxs = (int*)sm;
    float* b2s  = sm + SM_B2S;
    float* X2   = sm + SM_X2;
    float* B2p  = sm + SM_B2P;

    const int tid  = threadIdx.x;
    const int warp = tid >> 5, lane = tid & 31;
    const int g    = lane >> 2, tig = lane & 3;

    for (int i = tid; i < 8 * 4 * 32; i += 256) {
        int s  = i >> 7;
        int gp = (i >> 5) & 3;
        int ln = i & 31;
        int gg = ln >> 2, tt = ln & 3;
        int k0 = s * 8;
        int nA = gp * 16 + (gg >> 1) * 4 + (gg & 1);
        int nB = nA + 2;
        float4 v;
        v.x = tf32f(W2[(k0 + tt)     * 64 + nA]);
        v.y = tf32f(W2[(k0 + tt + 4) * 64 + nA]);
        v.z = tf32f(W2[(k0 + tt)     * 64 + nB]);
        v.w = tf32f(W2[(k0 + tt + 4) * 64 + nB]);
        *(float4*)&B2p[i * 4] = v;
    }
    if (tid < 64) b2s[tid] = b2[tid];
    __syncthreads();

    int*   widx = idxs + warp * 16;
    float* WX   = X2 + warp * 16 * XSTR;
    const float* xlo = WX + g * XSTR + tig * 2;
    const float* xhi = xlo + 8 * XSTR;
    const int qd = lane & 15;
    const int sp = lane >> 4;

    const int NG = E_EDGES / 16;
    const int gw0 = blockIdx.x * 8 + warp;
    const int gstr = gridDim.x * 8;

    for (int gi = gw0; gi < NG; gi += gstr) {
        // ---- fp16 gather (row + col) + silu -> WX frag-interleaved tf32 ----
        {
            int e = lane >> 1, half = lane & 1;
            int row  = srow[gi * 16 + e];
            int coln = scol[gi * 16 + e];
            if (half == 0) widx[e] = row;
            const uint4* pr = (const uint4*)(Phx + (size_t)row  * HID + half * 32);
            const uint4* pc = (const uint4*)(Phx + (size_t)coln * HID + 64 + half * 32);
            float* xr = WX + e * XSTR + half * 32;
#pragma unroll
            for (int bb = 0; bb < 4; bb++) {
                uint4 hr = pr[bb];
                uint4 hc = pc[bb];
                float2 r01 = h2f(hr.x), r23 = h2f(hr.y), r45 = h2f(hr.z), r67 = h2f(hr.w);
                float2 c01 = h2f(hc.x), c23 = h2f(hc.y), c45 = h2f(hc.z), c67 = h2f(hc.w);
                *(float2*)&xr[bb * 8 + 0] = make_float2(tf32f(silu(r01.x + c01.x)),
                                                        tf32f(silu(r45.x + c45.x)));
                *(float2*)&xr[bb * 8 + 2] = make_float2(tf32f(silu(r01.y + c01.y)),
                                                        tf32f(silu(r45.y + c45.y)));
                *(float2*)&xr[bb * 8 + 4] = make_float2(tf32f(silu(r23.x + c23.x)),
                                                        tf32f(silu(r67.x + c67.x)));
                *(float2*)&xr[bb * 8 + 6] = make_float2(tf32f(silu(r23.y + c23.y)),
                                                        tf32f(silu(r67.y + c67.y)));
            }
        }
        __syncwarp();

        // ---- MLP2 MMA ----
        float acc[8][4];
#pragma unroll
        for (int a = 0; a < 8; a++)
#pragma unroll
            for (int c = 0; c < 4; c++) acc[a][c] = 0.f;

#pragma unroll
        for (int s = 0; s < 8; s++) {
            float2 alo = *(const float2*)(xlo + s * 8);
            float2 ahi = *(const float2*)(xhi + s * 8);
            u32 a0 = __float_as_uint(alo.x), a1 = __float_as_uint(ahi.x);
            u32 a2 = __float_as_uint(alo.y), a3 = __float_as_uint(ahi.y);
#pragma unroll
            for (int gp = 0; gp < 4; gp++) {
                float4 bv = *(const float4*)&B2p[((s * 4 + gp) * 32 + lane) * 4];
                mma_tf32(acc[gp * 2 + 0], a0, a1, a2, a3,
                         __float_as_uint(bv.x), __float_as_uint(bv.y));
                mma_tf32(acc[gp * 2 + 1], a0, a1, a2, a3,
                         __float_as_uint(bv.z), __float_as_uint(bv.w));
            }
        }
        __syncwarp();

        // ---- write silu(D2 + b2) back into WX rows g, g+8 ----
        {
            float* rlo = WX + g * XSTR;
            float* rhi = WX + (g + 8) * XSTR;
#pragma unroll
            for (int gp = 0; gp < 4; gp++) {
                int c0 = gp * 16 + tig * 4;
                *(float2*)&rlo[c0]     = make_float2(silu(acc[gp*2][0]   + b2s[c0]),
                                                     silu(acc[gp*2][1]   + b2s[c0+1]));
                *(float2*)&rlo[c0 + 2] = make_float2(silu(acc[gp*2+1][0] + b2s[c0+2]),
                                                     silu(acc[gp*2+1][1] + b2s[c0+3]));
                *(float2*)&rhi[c0]     = make_float2(silu(acc[gp*2][2]   + b2s[c0]),
                                                     silu(acc[gp*2][3]   + b2s[c0+1]));
                *(float2*)&rhi[c0 + 2] = make_float2(silu(acc[gp*2+1][2] + b2s[c0+2]),
                                                     silu(acc[gp*2+1][3] + b2s[c0+3]));
            }
        }
        __syncwarp();

        // ---- segmented reduction: lane (qd, sp) walks 8 edges x 4 cols ----
        {
            int e0 = sp * 8;
            int cur = widx[e0];
            const float* r = WX + e0 * XSTR + qd * 4;
            float2 a01 = *(const float2*)(r);
            float2 a23 = *(const float2*)(r + 2);
            float s0 = a01.x, s1 = a01.y, s2 = a23.x, s3 = a23.y;
#pragma unroll
            for (int j = 1; j < 8; j++) {
                int rw = widx[e0 + j];
                const float* rr = WX + (e0 + j) * XSTR + qd * 4;
                float2 b01 = *(const float2*)(rr);
                float2 b23 = *(const float2*)(rr + 2);
                if (rw != cur) {
                    red4(g_agg + (size_t)cur * EH + qd * 4, s0, s1, s2, s3);
                    cur = rw;
                    s0 = b01.x; s1 = b01.y; s2 = b23.x; s3 = b23.y;
                } else {
                    s0 += b01.x; s1 += b01.y; s2 += b23.x; s3 += b23.y;
                }
            }
            red4(g_agg + (size_t)cur * EH + qd * 4, s0, s1, s2, s3);
        }
        __syncwarp();
    }
}

// ---------------------------------------------------------------------------
extern "C" void kernel_launch(void* const* d_in, const int* in_sizes, int n_in,
                              void* d_out, int out_size)
{
    const float* h_in  = (const float*)d_in[0];
    const int*   edges = (const int*)d_in[1];
    const float* W_in  = (const float*)d_in[2];
    const float* b_in  = (const float*)d_in[3];
    const float* eW1   = (const float*)d_in[4];
    const float* eb1   = (const float*)d_in[5];
    const float* eW2   = (const float*)d_in[6];
    const float* eb2   = (const float*)d_in[7];
    const float* nW1   = (const float*)d_in[8];
    const float* nb1   = (const float*)d_in[9];
    const float* nW2   = (const float*)d_in[10];
    const float* nb2   = (const float*)d_in[11];
    const float* W_out = (const float*)d_in[12];
    const float* b_out = (const float*)d_in[13];

    float*  ph;   cudaGetSymbolAddress((void**)&ph,   g_h);
    float*  pag;  cudaGetSymbolAddress((void**)&pag,  g_agg);
    float*  pz;   cudaGetSymbolAddress((void**)&pz,   g_z);
    __half* pphx; cudaGetSymbolAddress((void**)&pphx, g_phx);
    float*  pwc;  cudaGetSymbolAddress((void**)&pwc,  g_wcat);
    float*  pbc;  cudaGetSymbolAddress((void**)&pbc,  g_bcat);
    int* psrow;   cudaGetSymbolAddress((void**)&psrow, g_srow);
    int* pscol;   cudaGetSymbolAddress((void**)&pscol, g_scol);

    auto smem_g3 = [](int kdim) { return (kdim * 64 + 64 + 8 * 64 * 16) * 4; };
    const int sm_ei  = smem_g3(64);
    const int sm_p   = smem_g3(128);
    const int sm_m128 = (64 + 128 * XSTR + 16 * 4 * 32 * 4) * 4;
    const int sm_m192 = (64 + 128 * XSTR + 24 * 4 * 32 * 4) * 4;

    cudaFuncSetAttribute(edge_kernel2, cudaFuncAttributeMaxDynamicSharedMemorySize, SM_EDGE_BYTES);
    cudaFuncSetAttribute(node_mma<128, 128, false, false, true, true, true>,
                         cudaFuncAttributeMaxDynamicSharedMemorySize, sm_m128);
    cudaFuncSetAttribute(node_mma<192, 128, true, false, false, false, false>,
                         cudaFuncAttributeMaxDynamicSharedMemorySize, sm_m192);
    cudaFuncSetAttribute(node_mma<128, 128, false, true, false, false, false>,
                         cudaFuncAttributeMaxDynamicSharedMemorySize, sm_m128);
    cudaFuncSetAttribute(node_gemm3<64, 64, 128, false, false>,
                         cudaFuncAttributeMaxDynamicSharedMemorySize, sm_ei);
    cudaFuncSetAttribute(node_gemm3<128, 128, 64, false, false>,
                         cudaFuncAttributeMaxDynamicSharedMemorySize, sm_p);

    const int EB = (E_EDGES + 255) / 256;

    // sort edges by row + repack all layer-1 edge weights (once)
    k_zero_deg<<<SCAN_BLOCKS, 256>>>();
    k_hist<<<EB, 256>>>(edges);
    k_scan1<<<SCAN_BLOCKS, 256>>>();
    k_scan2<<<1, 256>>>();
    k_scan3<<<SCAN_BLOCKS, 256>>>();
    k_sort_scatter<<<EB, 256>>>(edges);
    k_repack<<<(L_LAYERS * HID * HID + 255) / 256, 256>>>(eW1, eb1);

    // embedding_in (fp32)
    node_gemm3<64, 64, 128, false, false><<<dim3(148, 2), 256, sm_ei>>>(
        h_in, nullptr, W_in, b_in, ph);

    for (int l = 0; l < L_LAYERS; l++) {
        // P = h @ [W1a|W1b] + [b1|0]  (tf32 mma; fp16-only output, zeroes agg)
        node_mma<128, 128, false, false, true, true, true><<<dim3(148, 2), 256, sm_m128>>>(
            ph, nullptr, pwc + l * HID * HID, pbc + l * HID, pz);
        edge_kernel2<<<444, 256, SM_EDGE_BYTES>>>(
            psrow, pscol, pphx, eW2 + l * EH * EH, eb2 + l * EH);
        // z = silu(concat(h, agg) @ nW1 + nb1)  (tf32 mma)
        node_mma<192, 128, true, false, false, false, false><<<dim3(148, 2), 256, sm_m192>>>(
            ph, pag, nW1 + l * (HID + EH) * HID, nb1 + l * HID, pz);
        // h = h + (z @ nW2 + nb2)  (tf32 mma, fp32 residual epilogue)
        node_mma<128, 128, false, true, false, false, false><<<dim3(148, 2), 256, sm_m128>>>(
            pz, nullptr, nW2 + l * HID * HID, nb2 + l * HID, ph);
    }

    // embedding_out (fp32)
    node_gemm3<128, 128, 64, false, false><<<dim3(148, 1), 256, sm_p>>>(
        ph, nullptr, W_out, b_out, (float*)d_out);
}

// round 14
// speedup vs baseline: 1.3101x; 1.0156x over previous
#include <cuda_runtime.h>
#include <cuda_bf16.h>
#include <cuda_fp16.h>
#include <cstdint>

// GNN_84421877170708: 4-layer GCL GNN. Round 14 (no numerics changes):
//  - sort chain forked onto a second stream (hidden under embed_in + P0)
//  - node_mma staging syncs -> __syncwarp (staging is warp-local)
//  - sorted edges packed as int2 (one LDG.64 per edge index pair)

#define N_NODES 50000
#define E_EDGES 800000
#define IN_NF   64
#define HID     128
#define EH      64
#define OUT_NF  64
#define L_LAYERS 4
#define XSTR    82
#define SCAN_BLOCKS ((N_NODES + 255) / 256)

__device__ float  g_h[N_NODES * HID];
__device__ float  g_agg[N_NODES * EH];
__device__ float  g_z[N_NODES * HID];
__device__ __half g_phx[N_NODES * HID];        // fp16 mirror of P
__device__ float  g_wcat[L_LAYERS * HID * HID];
__device__ float  g_bcat[L_LAYERS * HID];

__device__ int  g_deg[N_NODES];
__device__ int  g_base[N_NODES];
__device__ int  g_cursor[N_NODES];
__device__ int  g_bsums[256];
__device__ int2 g_sedge[E_EDGES];

using u64 = unsigned long long;
using u32 = unsigned int;

__device__ __forceinline__ float silu(float v) {
    float h = 0.5f * v, t;
    asm("tanh.approx.f32 %0, %1;" : "=f"(t) : "f"(h));
    return fmaf(h, t, h);
}
__device__ __forceinline__ u32 f2tf32(float f) {
    u32 r; asm("cvt.rna.tf32.f32 %0, %1;" : "=r"(r) : "f"(f)); return r;
}
__device__ __forceinline__ float tf32f(float f) {
    return __uint_as_float(f2tf32(f));
}
__device__ __forceinline__ void mma_tf32(float* c, u32 a0, u32 a1, u32 a2, u32 a3,
                                         u32 b0, u32 b1) {
    asm volatile(
        "mma.sync.aligned.m16n8k8.row.col.f32.tf32.tf32.f32 "
        "{%0,%1,%2,%3}, {%4,%5,%6,%7}, {%8,%9}, {%0,%1,%2,%3};"
        : "+f"(c[0]), "+f"(c[1]), "+f"(c[2]), "+f"(c[3])
        : "r"(a0), "r"(a1), "r"(a2), "r"(a3), "r"(b0), "r"(b1));
}
__device__ __forceinline__ void red4(float* p, float a, float b, float c, float d) {
    asm volatile("red.global.add.v4.f32 [%0], {%1,%2,%3,%4};"
                 :: "l"(p), "f"(a), "f"(b), "f"(c), "f"(d) : "memory");
}
__device__ __forceinline__ void ffma2(u64& acc, u64 x, u64 w) {
    asm("fma.rn.f32x2 %0, %1, %2, %0;" : "+l"(acc) : "l"(x), "l"(w));
}
__device__ __forceinline__ u64 pack2(float x) {
    u64 r; asm("mov.b64 %0, {%1, %1};" : "=l"(r) : "f"(x)); return r;
}
__device__ __forceinline__ u64 packf2(float a, float b) {
    u64 r; asm("mov.b64 %0, {%1, %2};" : "=l"(r) : "f"(a), "f"(b)); return r;
}
__device__ __forceinline__ float2 unpack2(u64 v) {
    float2 r; asm("mov.b64 {%0, %1}, %2;" : "=f"(r.x), "=f"(r.y) : "l"(v)); return r;
}
__device__ __forceinline__ float2 h2f(u32 h) {
    return __half22float2(*reinterpret_cast<const __half2*>(&h));
}

// ---------------------------------------------------------------------------
// counting sort of edges by row (runs on forked stream)
// ---------------------------------------------------------------------------
__global__ void k_zero_deg() {
    int i = blockIdx.x * 256 + threadIdx.x;
    if (i < N_NODES) { g_deg[i] = 0; g_cursor[i] = 0; }
}
__global__ void k_hist(const int* __restrict__ edges) {
    int e = blockIdx.x * 256 + threadIdx.x;
    if (e < E_EDGES) atomicAdd(&g_deg[edges[e]], 1);
}
__global__ void k_scan1() {
    __shared__ int s[256];
    int i = blockIdx.x * 256 + threadIdx.x;
    int v = (i < N_NODES) ? g_deg[i] : 0;
    s[threadIdx.x] = v;
    __syncthreads();
#pragma unroll
    for (int o = 1; o < 256; o <<= 1) {
        int t = (threadIdx.x >= o) ? s[threadIdx.x - o] : 0;
        __syncthreads();
        s[threadIdx.x] += t;
        __syncthreads();
    }
    if (i < N_NODES) g_base[i] = s[threadIdx.x] - v;
    if (threadIdx.x == 255) g_bsums[blockIdx.x] = s[255];
}
__global__ void k_scan2() {
    __shared__ int s[256];
    int i = threadIdx.x;
    int v = (i < SCAN_BLOCKS) ? g_bsums[i] : 0;
    s[i] = v;
    __syncthreads();
#pragma unroll
    for (int o = 1; o < 256; o <<= 1) {
        int t = (i >= o) ? s[i - o] : 0;
        __syncthreads();
        s[i] += t;
        __syncthreads();
    }
    g_bsums[i] = s[i] - v;
}
__global__ void k_scan3() {
    int i = blockIdx.x * 256 + threadIdx.x;
    if (i < N_NODES) g_base[i] += g_bsums[blockIdx.x];
}
__global__ void k_sort_scatter(const int* __restrict__ edges) {
    int e = blockIdx.x * 256 + threadIdx.x;
    if (e < E_EDGES) {
        int r = edges[e], c = edges[E_EDGES + e];
        int pos = g_base[r] + atomicAdd(&g_cursor[r], 1);
        g_sedge[pos] = make_int2(r, c);
    }
}

// ---------------------------------------------------------------------------
// repack ALL layers' W1 -> g_wcat[l][128x128], g_bcat[l] = [b1|0]  (once)
// ---------------------------------------------------------------------------
__global__ void k_repack(const float* __restrict__ eW1, const float* __restrict__ eb1) {
    int i = blockIdx.x * 256 + threadIdx.x;
    if (i < L_LAYERS * HID * HID) {
        int l = i >> 14, r = i & 16383;
        int k = r >> 7, j = r & 127;
        const float* w = eW1 + l * 2 * HID * EH;
        g_wcat[i] = (j < 64) ? w[k * 64 + j] : w[(k + 128) * 64 + (j - 64)];
    }
    if (i < L_LAYERS * HID) {
        int l = i >> 7, j = i & 127;
        g_bcat[i] = (j < 64) ? eb1[l * EH + j] : 0.f;
    }
}

// ---------------------------------------------------------------------------
// node_mma (tf32): res = act(concat(in1,in2) @ W[:, yoff:+64] + b)
//   warp-local staging -> __syncwarp in main loop.
// ---------------------------------------------------------------------------
template<int KDIM, int W1IN, bool DO_SILU, bool DO_RES, bool WRITE_H, bool SKIP_OUT, bool ZERO_AGG>
__global__ void __launch_bounds__(256, 2) node_mma(
    const float* __restrict__ in1, const float* __restrict__ in2,
    const float* __restrict__ W, const float* __restrict__ b,
    float* __restrict__ out)
{
    constexpr int NSTEP = KDIM / 8;
    extern __shared__ float sm[];
    float* bs = sm;
    float* X  = sm + 64;
    float* Bp = X + 128 * XSTR;

    const int tid  = threadIdx.x;
    const int warp = tid >> 5, lane = tid & 31;
    const int g    = lane >> 2, tig = lane & 3;
    const int yoff = blockIdx.y * 64;

    for (int i = tid; i < NSTEP * 4 * 32; i += 256) {
        int s  = i >> 7;
        int gp = (i >> 5) & 3;
        int ln = i & 31;
        int gg = ln >> 2, tt = ln & 3;
        int k0 = s * 8;
        int nA = yoff + gp * 16 + (gg >> 1) * 4 + (gg & 1);
        int nB = nA + 2;
        float4 v;
        v.x = tf32f(W[(size_t)(k0 + tt)     * HID + nA]);
        v.y = tf32f(W[(size_t)(k0 + tt + 4) * HID + nA]);
        v.z = tf32f(W[(size_t)(k0 + tt)     * HID + nB]);
        v.w = tf32f(W[(size_t)(k0 + tt + 4) * HID + nB]);
        *(float4*)&Bp[i * 4] = v;
    }
    if (tid < 64) bs[tid] = b[yoff + tid];
    __syncthreads();   // Bp/bs ready for all warps (staging itself is warp-local)

    const float* xlo = X + (warp * 16 + g) * XSTR + tig * 2;
    const float* xhi = xlo + 8 * XSTR;
    const int e  = tid >> 1;
    const int hf = tid & 1;

    const int NTILES = (N_NODES + 127) / 128;
    for (int t = blockIdx.x; t < NTILES; t += gridDim.x) {
        const int tb = t * 128;
        int node = tb + e;
        if (node >= N_NODES) node = 0;

        if (ZERO_AGG && blockIdx.y == 0) {
            float4* az = (float4*)g_agg;
            int f0 = tb * 16 + tid * 8;
#pragma unroll
            for (int i = 0; i < 8; i++) {
                int f = f0 + i;
                if (f < N_NODES * 16) az[f] = make_float4(0.f, 0.f, 0.f, 0.f);
            }
        }

        float acc[8][4];
#pragma unroll
        for (int a = 0; a < 8; a++)
#pragma unroll
            for (int c = 0; c < 4; c++) acc[a][c] = 0.f;

#pragma unroll
        for (int c0 = 0; c0 < KDIM; c0 += 64) {
            __syncwarp();   // this warp's prior reads of X done
            {
                const int kb = c0 + hf * 32;
                const float4* src;
                if (KDIM == W1IN || kb < W1IN)
                    src = (const float4*)(in1 + (size_t)node * W1IN + kb);
                else
                    src = (const float4*)(in2 + (size_t)node * (KDIM - W1IN) + (kb - W1IN));
                float* xr = X + e * XSTR + hf * 32;
#pragma unroll
                for (int bb = 0; bb < 4; bb++) {
                    float4 x0 = src[2 * bb];
                    float4 x1 = src[2 * bb + 1];
                    *(float2*)&xr[bb * 8 + 0] = make_float2(tf32f(x0.x), tf32f(x1.x));
                    *(float2*)&xr[bb * 8 + 2] = make_float2(tf32f(x0.y), tf32f(x1.y));
                    *(float2*)&xr[bb * 8 + 4] = make_float2(tf32f(x0.z), tf32f(x1.z));
                    *(float2*)&xr[bb * 8 + 6] = make_float2(tf32f(x0.w), tf32f(x1.w));
                }
            }
            __syncwarp();   // this warp's staging visible to itself

#pragma unroll
            for (int s8 = 0; s8 < 8; s8++) {
                const int s = (c0 >> 3) + s8;
                float2 alo = *(const float2*)(xlo + s8 * 8);
                float2 ahi = *(const float2*)(xhi + s8 * 8);
                u32 a0 = __float_as_uint(alo.x), a1 = __float_as_uint(ahi.x);
                u32 a2 = __float_as_uint(alo.y), a3 = __float_as_uint(ahi.y);
#pragma unroll
                for (int gp = 0; gp < 4; gp++) {
                    float4 bv = *(const float4*)&Bp[((s * 4 + gp) * 32 + lane) * 4];
                    mma_tf32(acc[gp * 2 + 0], a0, a1, a2, a3,
                             __float_as_uint(bv.x), __float_as_uint(bv.y));
                    mma_tf32(acc[gp * 2 + 1], a0, a1, a2, a3,
                             __float_as_uint(bv.z), __float_as_uint(bv.w));
                }
            }
        }

        {
            int r0 = tb + warp * 16 + g;
            int r1 = r0 + 8;
#pragma unroll
            for (int gp = 0; gp < 4; gp++) {
                int c0 = gp * 16 + tig * 4;
                float4 v0 = make_float4(acc[gp*2][0]   + bs[c0],
                                        acc[gp*2][1]   + bs[c0+1],
                                        acc[gp*2+1][0] + bs[c0+2],
                                        acc[gp*2+1][1] + bs[c0+3]);
                float4 v1 = make_float4(acc[gp*2][2]   + bs[c0],
                                        acc[gp*2][3]   + bs[c0+1],
                                        acc[gp*2+1][2] + bs[c0+2],
                                        acc[gp*2+1][3] + bs[c0+3]);
                if (DO_SILU) {
                    v0.x = silu(v0.x); v0.y = silu(v0.y); v0.z = silu(v0.z); v0.w = silu(v0.w);
                    v1.x = silu(v1.x); v1.y = silu(v1.y); v1.z = silu(v1.z); v1.w = silu(v1.w);
                }
                if (r0 < N_NODES) {
                    if (!SKIP_OUT) {
                        float* dst = out + (size_t)r0 * HID + yoff + c0;
                        if (DO_RES) {
                            float4 r = *(const float4*)dst;
                            v0.x += r.x; v0.y += r.y; v0.z += r.z; v0.w += r.w;
                        }
                        *(float4*)dst = v0;
                    }
                    if (WRITE_H) {
                        __half2* d = (__half2*)(g_phx + (size_t)r0 * HID + yoff + c0);
                        d[0] = __floats2half2_rn(v0.x, v0.y);
                        d[1] = __floats2half2_rn(v0.z, v0.w);
                    }
                }
                if (r1 < N_NODES) {
                    if (!SKIP_OUT) {
                        float* dst = out + (size_t)r1 * HID + yoff + c0;
                        if (DO_RES) {
                            float4 r = *(const float4*)dst;
                            v1.x += r.x; v1.y += r.y; v1.z += r.z; v1.w += r.w;
                        }
                        *(float4*)dst = v1;
                    }
                    if (WRITE_H) {
                        __half2* d = (__half2*)(g_phx + (size_t)r1 * HID + yoff + c0);
                        d[0] = __floats2half2_rn(v1.x, v1.y);
                        d[1] = __floats2half2_rn(v1.z, v1.w);
                    }
                }
            }
        }
    }
}

// ---------------------------------------------------------------------------
// node_gemm3 (fp32, embeddings only)
// ---------------------------------------------------------------------------
template<int KDIM, int W1IN, int NOUT_TOTAL, bool DO_SILU, bool DO_RES>
__global__ void __launch_bounds__(256, 2) node_gemm3(
    const float* __restrict__ in1, const float* __restrict__ in2,
    const float* __restrict__ W, const float* __restrict__ b,
    float* __restrict__ out)
{
    extern __shared__ float fsmem[];
    float* ws = fsmem;
    float* bs = ws + KDIM * 64;
    float* stg = bs + 64;

    const int tid  = threadIdx.x;
    const int warp = tid >> 5;
    const int lane = tid & 31;
    const int yoff = blockIdx.y * 64;

    for (int i = tid * 4; i < KDIM * 64; i += 1024) {
        int k = i >> 6, j = i & 63;
        *(float4*)&ws[i] = *(const float4*)(W + (size_t)k * NOUT_TOTAL + yoff + j);
    }
    if (tid < 64) bs[tid] = b[yoff + tid];
    __syncthreads();

    float* xs = stg + warp * (64 * 16);
    const int p    = lane >> 2;
    const int q    = lane & 3;
    const int m    = lane >> 1;
    const int half = lane & 1;

    u64 biasr[4];
#pragma unroll
    for (int g = 0; g < 4; g++)
        biasr[g] = packf2(bs[p * 8 + 2 * g], bs[p * 8 + 2 * g + 1]);

    const int gw     = blockIdx.x * 8 + warp;
    const int nwarps = gridDim.x * 8;
    const int ntiles = N_NODES / 16;

    for (int t = gw; t < ntiles; t += nwarps) {
        const int node = t * 16 + m;
        const float* s1 = in1 + (size_t)node * W1IN;
        const float* s2 = (KDIM > W1IN) ? in2 + (size_t)node * (KDIM - W1IN) : nullptr;

        u64 acc[4][4];
#pragma unroll
        for (int d = 0; d < 4; d++)
#pragma unroll
            for (int g = 0; g < 4; g++) acc[d][g] = biasr[g];

#pragma unroll
        for (int c0 = 0; c0 < KDIM; c0 += 64) {
            __syncwarp();
#pragma unroll
            for (int i = 0; i < 8; i++) {
                int kk = c0 + half * 32 + i * 4;
                float4 v;
                if (KDIM == W1IN || kk < W1IN) v = *(const float4*)(s1 + kk);
                else                           v = *(const float4*)(s2 + (kk - W1IN));
                int kl = kk - c0;
                xs[(kl + 0) * 16 + m] = v.x;
                xs[(kl + 1) * 16 + m] = v.y;
                xs[(kl + 2) * 16 + m] = v.z;
                xs[(kl + 3) * 16 + m] = v.w;
            }
            __syncwarp();

#pragma unroll 4
            for (int k = 0; k < 64; k++) {
                float4 xv = *(const float4*)&xs[k * 16 + q * 4];
                const ulonglong2* wp = (const ulonglong2*)(ws + (c0 + k) * 64 + p * 8);
                ulonglong2 wa = wp[0];
                ulonglong2 wb = wp[1];
                u64 xp[4] = {pack2(xv.x), pack2(xv.y), pack2(xv.z), pack2(xv.w)};
#pragma unroll
                for (int d = 0; d < 4; d++) {
                    ffma2(acc[d][0], xp[d], wa.x);
                    ffma2(acc[d][1], xp[d], wa.y);
                    ffma2(acc[d][2], xp[d], wb.x);
                    ffma2(acc[d][3], xp[d], wb.y);
                }
            }
        }

#pragma unroll
        for (int d = 0; d < 4; d++) {
            int nn = t * 16 + q * 4 + d;
            float* dst = out + (size_t)nn * NOUT_TOTAL + yoff + p * 8;
#pragma unroll
            for (int g = 0; g < 2; g++) {
                float2 a = unpack2(acc[d][2 * g]);
                float2 c = unpack2(acc[d][2 * g + 1]);
                float4 v = make_float4(a.x, a.y, c.x, c.y);
                if (DO_SILU) {
                    v.x = silu(v.x); v.y = silu(v.y);
                    v.z = silu(v.z); v.w = silu(v.w);
                }
                if (DO_RES) {
                    float4 r = *(const float4*)(dst + g * 4);
                    v.x += r.x; v.y += r.y; v.z += r.z; v.w += r.w;
                }
                *(float4*)(dst + g * 4) = v;
            }
        }
    }
}

// ---------------------------------------------------------------------------
// Edge kernel: warp-autonomous 16-edge groups; full fp16 gather (g_phx) ->
// silu -> tf32 mma -> writeback -> segmented reduction -> red4 per run.
// ---------------------------------------------------------------------------
#define SM_B2S  128
#define SM_X2   192
#define SM_B2P  (192 + 128 * XSTR)
#define SM_EDGE_FLOATS (SM_B2P + 8 * 4 * 32 * 4)
#define SM_EDGE_BYTES  (SM_EDGE_FLOATS * 4)

__global__ void __launch_bounds__(256, 3)
edge_kernel2(const int2* __restrict__ sedge,
             const __half* __restrict__ Phx,
             const float* __restrict__ W2, const float* __restrict__ b2)
{
    extern __shared__ float sm[];
    int*   idxs = (int*)sm;
    float* b2s  = sm + SM_B2S;
    float* X2   = sm + SM_X2;
    float* B2p  = sm + SM_B2P;

    const int tid  = threadIdx.x;
    const int warp = tid >> 5, lane = tid & 31;
    const int g    = lane >> 2, tig = lane & 3;

    for (int i = tid; i < 8 * 4 * 32; i += 256) {
        int s  = i >> 7;
        int gp = (i >> 5) & 3;
        int ln = i & 31;
        int gg = ln >> 2, tt = ln & 3;
        int k0 = s * 8;
        int nA = gp * 16 + (gg >> 1) * 4 + (gg & 1);
        int nB = nA + 2;
        float4 v;
        v.x = tf32f(W2[(k0 + tt)     * 64 + nA]);
        v.y = tf32f(W2[(k0 + tt + 4) * 64 + nA]);
        v.z = tf32f(W2[(k0 + tt)     * 64 + nB]);
        v.w = tf32f(W2[(k0 + tt + 4) * 64 + nB]);
        *(float4*)&B2p[i * 4] = v;
    }
    if (tid < 64) b2s[tid] = b2[tid];
    __syncthreads();

    int*   widx = idxs + warp * 16;
    float* WX   = X2 + warp * 16 * XSTR;
    const float* xlo = WX + g * XSTR + tig * 2;
    const float* xhi = xlo + 8 * XSTR;
    const int qd = lane & 15;
    const int sp = lane >> 4;

    const int NG = E_EDGES / 16;
    const int gw0 = blockIdx.x * 8 + warp;
    const int gstr = gridDim.x * 8;

    for (int gi = gw0; gi < NG; gi += gstr) {
        // ---- fp16 gather (row + col) + silu -> WX frag-interleaved tf32 ----
        {
            int e = lane >> 1, half = lane & 1;
            int2 rc = sedge[gi * 16 + e];
            if (half == 0) widx[e] = rc.x;
            const uint4* pr = (const uint4*)(Phx + (size_t)rc.x * HID + half * 32);
            const uint4* pc = (const uint4*)(Phx + (size_t)rc.y * HID + 64 + half * 32);
            float* xr = WX + e * XSTR + half * 32;
#pragma unroll
            for (int bb = 0; bb < 4; bb++) {
                uint4 hr = pr[bb];
                uint4 hc = pc[bb];
                float2 r01 = h2f(hr.x), r23 = h2f(hr.y), r45 = h2f(hr.z), r67 = h2f(hr.w);
                float2 c01 = h2f(hc.x), c23 = h2f(hc.y), c45 = h2f(hc.z), c67 = h2f(hc.w);
                *(float2*)&xr[bb * 8 + 0] = make_float2(tf32f(silu(r01.x + c01.x)),
                                                        tf32f(silu(r45.x + c45.x)));
                *(float2*)&xr[bb * 8 + 2] = make_float2(tf32f(silu(r01.y + c01.y)),
                                                        tf32f(silu(r45.y + c45.y)));
                *(float2*)&xr[bb * 8 + 4] = make_float2(tf32f(silu(r23.x + c23.x)),
                                                        tf32f(silu(r67.x + c67.x)));
                *(float2*)&xr[bb * 8 + 6] = make_float2(tf32f(silu(r23.y + c23.y)),
                                                        tf32f(silu(r67.y + c67.y)));
            }
        }
        __syncwarp();

        // ---- MLP2 MMA ----
        float acc[8][4];
#pragma unroll
        for (int a = 0; a < 8; a++)
#pragma unroll
            for (int c = 0; c < 4; c++) acc[a][c] = 0.f;

#pragma unroll
        for (int s = 0; s < 8; s++) {
            float2 alo = *(const float2*)(xlo + s * 8);
            float2 ahi = *(const float2*)(xhi + s * 8);
            u32 a0 = __float_as_uint(alo.x), a1 = __float_as_uint(ahi.x);
            u32 a2 = __float_as_uint(alo.y), a3 = __float_as_uint(ahi.y);
#pragma unroll
            for (int gp = 0; gp < 4; gp++) {
                float4 bv = *(const float4*)&B2p[((s * 4 + gp) * 32 + lane) * 4];
                mma_tf32(acc[gp * 2 + 0], a0, a1, a2, a3,
                         __float_as_uint(bv.x), __float_as_uint(bv.y));
                mma_tf32(acc[gp * 2 + 1], a0, a1, a2, a3,
                         __float_as_uint(bv.z), __float_as_uint(bv.w));
            }
        }
        __syncwarp();

        // ---- write silu(D2 + b2) back into WX rows g, g+8 ----
        {
            float* rlo = WX + g * XSTR;
            float* rhi = WX + (g + 8) * XSTR;
#pragma unroll
            for (int gp = 0; gp < 4; gp++) {
                int c0 = gp * 16 + tig * 4;
                *(float2*)&rlo[c0]     = make_float2(silu(acc[gp*2][0]   + b2s[c0]),
                                                     silu(acc[gp*2][1]   + b2s[c0+1]));
                *(float2*)&rlo[c0 + 2] = make_float2(silu(acc[gp*2+1][0] + b2s[c0+2]),
                                                     silu(acc[gp*2+1][1] + b2s[c0+3]));
                *(float2*)&rhi[c0]     = make_float2(silu(acc[gp*2][2]   + b2s[c0]),
                                                     silu(acc[gp*2][3]   + b2s[c0+1]));
                *(float2*)&rhi[c0 + 2] = make_float2(silu(acc[gp*2+1][2] + b2s[c0+2]),
                                                     silu(acc[gp*2+1][3] + b2s[c0+3]));
            }
        }
        __syncwarp();

        // ---- segmented reduction: lane (qd, sp) walks 8 edges x 4 cols ----
        {
            int e0 = sp * 8;
            int cur = widx[e0];
            const float* r = WX + e0 * XSTR + qd * 4;
            float2 a01 = *(const float2*)(r);
            float2 a23 = *(const float2*)(r + 2);
            float s0 = a01.x, s1 = a01.y, s2 = a23.x, s3 = a23.y;
#pragma unroll
            for (int j = 1; j < 8; j++) {
                int rw = widx[e0 + j];
                const float* rr = WX + (e0 + j) * XSTR + qd * 4;
                float2 b01 = *(const float2*)(rr);
                float2 b23 = *(const float2*)(rr + 2);
                if (rw != cur) {
                    red4(g_agg + (size_t)cur * EH + qd * 4, s0, s1, s2, s3);
                    cur = rw;
                    s0 = b01.x; s1 = b01.y; s2 = b23.x; s3 = b23.y;
                } else {
                    s0 += b01.x; s1 += b01.y; s2 += b23.x; s3 += b23.y;
                }
            }
            red4(g_agg + (size_t)cur * EH + qd * 4, s0, s1, s2, s3);
        }
        __syncwarp();
    }
}

// ---------------------------------------------------------------------------
extern "C" void kernel_launch(void* const* d_in, const int* in_sizes, int n_in,
                              void* d_out, int out_size)
{
    const float* h_in  = (const float*)d_in[0];
    const int*   edges = (const int*)d_in[1];
    const float* W_in  = (const float*)d_in[2];
    const float* b_in  = (const float*)d_in[3];
    const float* eW1   = (const float*)d_in[4];
    const float* eb1   = (const float*)d_in[5];
    const float* eW2   = (const float*)d_in[6];
    const float* eb2   = (const float*)d_in[7];
    const float* nW1   = (const float*)d_in[8];
    const float* nb1   = (const float*)d_in[9];
    const float* nW2   = (const float*)d_in[10];
    const float* nb2   = (const float*)d_in[11];
    const float* W_out = (const float*)d_in[12];
    const float* b_out = (const float*)d_in[13];

    float*  ph;   cudaGetSymbolAddress((void**)&ph,   g_h);
    float*  pag;  cudaGetSymbolAddress((void**)&pag,  g_agg);
    float*  pz;   cudaGetSymbolAddress((void**)&pz,   g_z);
    __half* pphx; cudaGetSymbolAddress((void**)&pphx, g_phx);
    float*  pwc;  cudaGetSymbolAddress((void**)&pwc,  g_wcat);
    float*  pbc;  cudaGetSymbolAddress((void**)&pbc,  g_bcat);
    int2*   pse;  cudaGetSymbolAddress((void**)&pse,  g_sedge);

    auto smem_g3 = [](int kdim) { return (kdim * 64 + 64 + 8 * 64 * 16) * 4; };
    const int sm_ei  = smem_g3(64);
    const int sm_p   = smem_g3(128);
    const int sm_m128 = (64 + 128 * XSTR + 16 * 4 * 32 * 4) * 4;
    const int sm_m192 = (64 + 128 * XSTR + 24 * 4 * 32 * 4) * 4;

    cudaFuncSetAttribute(edge_kernel2, cudaFuncAttributeMaxDynamicSharedMemorySize, SM_EDGE_BYTES);
    cudaFuncSetAttribute(node_mma<128, 128, false, false, true, true, true>,
                         cudaFuncAttributeMaxDynamicSharedMemorySize, sm_m128);
    cudaFuncSetAttribute(node_mma<192, 128, true, false, false, false, false>,
                         cudaFuncAttributeMaxDynamicSharedMemorySize, sm_m192);
    cudaFuncSetAttribute(node_mma<128, 128, false, true, false, false, false>,
                         cudaFuncAttributeMaxDynamicSharedMemorySize, sm_m128);
    cudaFuncSetAttribute(node_gemm3<64, 64, 128, false, false>,
                         cudaFuncAttributeMaxDynamicSharedMemorySize, sm_ei);
    cudaFuncSetAttribute(node_gemm3<128, 128, 64, false, false>,
                         cudaFuncAttributeMaxDynamicSharedMemorySize, sm_p);

    const int EB = (E_EDGES + 255) / 256;

    // Lazily-created fork stream + events (host resources only; created once,
    // before the capture call, so the captured graph is identical every call).
    static cudaStream_t s2 = nullptr;
    static cudaEvent_t ev_fork = nullptr, ev_join = nullptr;
    if (s2 == nullptr) {
        cudaStreamCreateWithFlags(&s2, cudaStreamNonBlocking);
        cudaEventCreateWithFlags(&ev_fork, cudaEventDisableTiming);
        cudaEventCreateWithFlags(&ev_join, cudaEventDisableTiming);
    }

    // ---- fork: edge sort on s2, overlapped with repack/embed_in/P(l0) ----
    cudaEventRecord(ev_fork, 0);
    cudaStreamWaitEvent(s2, ev_fork, 0);
    k_zero_deg<<<SCAN_BLOCKS, 256, 0, s2>>>();
    k_hist<<<EB, 256, 0, s2>>>(edges);
    k_scan1<<<SCAN_BLOCKS, 256, 0, s2>>>();
    k_scan2<<<1, 256, 0, s2>>>();
    k_scan3<<<SCAN_BLOCKS, 256, 0, s2>>>();
    k_sort_scatter<<<EB, 256, 0, s2>>>(edges);
    cudaEventRecord(ev_join, s2);

    // ---- legacy stream: weight repack + embedding_in + P(l=0) ----
    k_repack<<<(L_LAYERS * HID * HID + 255) / 256, 256>>>(eW1, eb1);
    node_gemm3<64, 64, 128, false, false><<<dim3(148, 2), 256, sm_ei>>>(
        h_in, nullptr, W_in, b_in, ph);

    for (int l = 0; l < L_LAYERS; l++) {
        // P = h @ [W1a|W1b] + [b1|0]  (tf32 mma; fp16-only output, zeroes agg)
        node_mma<128, 128, false, false, true, true, true><<<dim3(148, 2), 256, sm_m128>>>(
            ph, nullptr, pwc + l * HID * HID, pbc + l * HID, pz);
        if (l == 0) cudaStreamWaitEvent(0, ev_join, 0);   // sorted edges ready
        edge_kernel2<<<444, 256, SM_EDGE_BYTES>>>(
            pse, pphx, eW2 + l * EH * EH, eb2 + l * EH);
        // z = silu(concat(h, agg) @ nW1 + nb1)  (tf32 mma)
        node_mma<192, 128, true, false, false, false, false><<<dim3(148, 2), 256, sm_m192>>>(
            ph, pag, nW1 + l * (HID + EH) * HID, nb1 + l * HID, pz);
        // h = h + (z @ nW2 + nb2)  (tf32 mma, fp32 residual epilogue)
        node_mma<128, 128, false, true, false, false, false><<<dim3(148, 2), 256, sm_m128>>>(
            pz, nullptr, nW2 + l * HID * HID, nb2 + l * HID, ph);
    }

    // embedding_out (fp32)
    node_gemm3<128, 128, 64, false, false><<<dim3(148, 1), 256, sm_p>>>(
        ph, nullptr, W_out, b_out, (float*)d_out);
}

// round 15
// speedup vs baseline: 1.3127x; 1.0020x over previous
#include <cuda_runtime.h>
#include <cuda_bf16.h>
#include <cuda_fp16.h>
#include <cstdint>

// GNN_84421877170708: 4-layer GCL GNN. Round 14 (no numerics changes):
//  - sort chain forked onto a second stream (hidden under embed_in + P0)
//  - node_mma staging syncs -> __syncwarp (staging is warp-local)
//  - sorted edges packed as int2 (one LDG.64 per edge index pair)

#define N_NODES 50000
#define E_EDGES 800000
#define IN_NF   64
#define HID     128
#define EH      64
#define OUT_NF  64
#define L_LAYERS 4
#define XSTR    82
#define SCAN_BLOCKS ((N_NODES + 255) / 256)

__device__ float  g_h[N_NODES * HID];
__device__ float  g_agg[N_NODES * EH];
__device__ float  g_z[N_NODES * HID];
__device__ __half g_phx[N_NODES * HID];        // fp16 mirror of P
__device__ float  g_wcat[L_LAYERS * HID * HID];
__device__ float  g_bcat[L_LAYERS * HID];

__device__ int  g_deg[N_NODES];
__device__ int  g_base[N_NODES];
__device__ int  g_cursor[N_NODES];
__device__ int  g_bsums[256];
__device__ int2 g_sedge[E_EDGES];

using u64 = unsigned long long;
using u32 = unsigned int;

__device__ __forceinline__ float silu(float v) {
    float h = 0.5f * v, t;
    asm("tanh.approx.f32 %0, %1;" : "=f"(t) : "f"(h));
    return fmaf(h, t, h);
}
__device__ __forceinline__ u32 f2tf32(float f) {
    u32 r; asm("cvt.rna.tf32.f32 %0, %1;" : "=r"(r) : "f"(f)); return r;
}
__device__ __forceinline__ float tf32f(float f) {
    return __uint_as_float(f2tf32(f));
}
__device__ __forceinline__ void mma_tf32(float* c, u32 a0, u32 a1, u32 a2, u32 a3,
                                         u32 b0, u32 b1) {
    asm volatile(
        "mma.sync.aligned.m16n8k8.row.col.f32.tf32.tf32.f32 "
        "{%0,%1,%2,%3}, {%4,%5,%6,%7}, {%8,%9}, {%0,%1,%2,%3};"
        : "+f"(c[0]), "+f"(c[1]), "+f"(c[2]), "+f"(c[3])
        : "r"(a0), "r"(a1), "r"(a2), "r"(a3), "r"(b0), "r"(b1));
}
__device__ __forceinline__ void red4(float* p, float a, float b, float c, float d) {
    asm volatile("red.global.add.v4.f32 [%0], {%1,%2,%3,%4};"
                 :: "l"(p), "f"(a), "f"(b), "f"(c), "f"(d) : "memory");
}
__device__ __forceinline__ void ffma2(u64& acc, u64 x, u64 w) {
    asm("fma.rn.f32x2 %0, %1, %2, %0;" : "+l"(acc) : "l"(x), "l"(w));
}
__device__ __forceinline__ u64 pack2(float x) {
    u64 r; asm("mov.b64 %0, {%1, %1};" : "=l"(r) : "f"(x)); return r;
}
__device__ __forceinline__ u64 packf2(float a, float b) {
    u64 r; asm("mov.b64 %0, {%1, %2};" : "=l"(r) : "f"(a), "f"(b)); return r;
}
__device__ __forceinline__ float2 unpack2(u64 v) {
    float2 r; asm("mov.b64 {%0, %1}, %2;" : "=f"(r.x), "=f"(r.y) : "l"(v)); return r;
}
__device__ __forceinline__ float2 h2f(u32 h) {
    return __half22float2(*reinterpret_cast<const __half2*>(&h));
}

// ---------------------------------------------------------------------------
// counting sort of edges by row (runs on forked stream)
// ---------------------------------------------------------------------------
__global__ void k_zero_deg() {
    int i = blockIdx.x * 256 + threadIdx.x;
    if (i < N_NODES) { g_deg[i] = 0; g_cursor[i] = 0; }
}
__global__ void k_hist(const int* __restrict__ edges) {
    int e = blockIdx.x * 256 + threadIdx.x;
    if (e < E_EDGES) atomicAdd(&g_deg[edges[e]], 1);
}
__global__ void k_scan1() {
    __shared__ int s[256];
    int i = blockIdx.x * 256 + threadIdx.x;
    int v = (i < N_NODES) ? g_deg[i] : 0;
    s[threadIdx.x] = v;
    __syncthreads();
#pragma unroll
    for (int o = 1; o < 256; o <<= 1) {
        int t = (threadIdx.x >= o) ? s[threadIdx.x - o] : 0;
        __syncthreads();
        s[threadIdx.x] += t;
        __syncthreads();
    }
    if (i < N_NODES) g_base[i] = s[threadIdx.x] - v;
    if (threadIdx.x == 255) g_bsums[blockIdx.x] = s[255];
}
__global__ void k_scan2() {
    __shared__ int s[256];
    int i = threadIdx.x;
    int v = (i < SCAN_BLOCKS) ? g_bsums[i] : 0;
    s[i] = v;
    __syncthreads();
#pragma unroll
    for (int o = 1; o < 256; o <<= 1) {
        int t = (i >= o) ? s[i - o] : 0;
        __syncthreads();
        s[i] += t;
        __syncthreads();
    }
    g_bsums[i] = s[i] - v;
}
__global__ void k_scan3() {
    int i = blockIdx.x * 256 + threadIdx.x;
    if (i < N_NODES) g_base[i] += g_bsums[blockIdx.x];
}
__global__ void k_sort_scatter(const int* __restrict__ edges) {
    int e = blockIdx.x * 256 + threadIdx.x;
    if (e < E_EDGES) {
        int r = edges[e], c = edges[E_EDGES + e];
        int pos = g_base[r] + atomicAdd(&g_cursor[r], 1);
        g_sedge[pos] = make_int2(r, c);
    }
}

// ---------------------------------------------------------------------------
// repack ALL layers' W1 -> g_wcat[l][128x128], g_bcat[l] = [b1|0]  (once)
// ---------------------------------------------------------------------------
__global__ void k_repack(const float* __restrict__ eW1, const float* __restrict__ eb1) {
    int i = blockIdx.x * 256 + threadIdx.x;
    if (i < L_LAYERS * HID * HID) {
        int l = i >> 14, r = i & 16383;
        int k = r >> 7, j = r & 127;
        const float* w = eW1 + l * 2 * HID * EH;
        g_wcat[i] = (j < 64) ? w[k * 64 + j] : w[(k + 128) * 64 + (j - 64)];
    }
    if (i < L_LAYERS * HID) {
        int l = i >> 7, j = i & 127;
        g_bcat[i] = (j < 64) ? eb1[l * EH + j] : 0.f;
    }
}

// ---------------------------------------------------------------------------
// node_mma (tf32): res = act(concat(in1,in2) @ W[:, yoff:+64] + b)
//   warp-local staging -> __syncwarp in main loop.
// ---------------------------------------------------------------------------
template<int KDIM, int W1IN, bool DO_SILU, bool DO_RES, bool WRITE_H, bool SKIP_OUT, bool ZERO_AGG>
__global__ void __launch_bounds__(256, 2) node_mma(
    const float* __restrict__ in1, const float* __restrict__ in2,
    const float* __restrict__ W, const float* __restrict__ b,
    float* __restrict__ out)
{
    constexpr int NSTEP = KDIM / 8;
    extern __shared__ float sm[];
    float* bs = sm;
    float* X  = sm + 64;
    float* Bp = X + 128 * XSTR;

    const int tid  = threadIdx.x;
    const int warp = tid >> 5, lane = tid & 31;
    const int g    = lane >> 2, tig = lane & 3;
    const int yoff = blockIdx.y * 64;

    for (int i = tid; i < NSTEP * 4 * 32; i += 256) {
        int s  = i >> 7;
        int gp = (i >> 5) & 3;
        int ln = i & 31;
        int gg = ln >> 2, tt = ln & 3;
        int k0 = s * 8;
        int nA = yoff + gp * 16 + (gg >> 1) * 4 + (gg & 1);
        int nB = nA + 2;
        float4 v;
        v.x = tf32f(W[(size_t)(k0 + tt)     * HID + nA]);
        v.y = tf32f(W[(size_t)(k0 + tt + 4) * HID + nA]);
        v.z = tf32f(W[(size_t)(k0 + tt)     * HID + nB]);
        v.w = tf32f(W[(size_t)(k0 + tt + 4) * HID + nB]);
        *(float4*)&Bp[i * 4] = v;
    }
    if (tid < 64) bs[tid] = b[yoff + tid];
    __syncthreads();   // Bp/bs ready for all warps (staging itself is warp-local)

    const float* xlo = X + (warp * 16 + g) * XSTR + tig * 2;
    const float* xhi = xlo + 8 * XSTR;
    const int e  = tid >> 1;
    const int hf = tid & 1;

    const int NTILES = (N_NODES + 127) / 128;
    for (int t = blockIdx.x; t < NTILES; t += gridDim.x) {
        const int tb = t * 128;
        int node = tb + e;
        if (node >= N_NODES) node = 0;

        if (ZERO_AGG && blockIdx.y == 0) {
            float4* az = (float4*)g_agg;
            int f0 = tb * 16 + tid * 8;
#pragma unroll
            for (int i = 0; i < 8; i++) {
                int f = f0 + i;
                if (f < N_NODES * 16) az[f] = make_float4(0.f, 0.f, 0.f, 0.f);
            }
        }

        float acc[8][4];
#pragma unroll
        for (int a = 0; a < 8; a++)
#pragma unroll
            for (int c = 0; c < 4; c++) acc[a][c] = 0.f;

#pragma unroll
        for (int c0 = 0; c0 < KDIM; c0 += 64) {
            __syncwarp();   // this warp's prior reads of X done
            {
                const int kb = c0 + hf * 32;
                const float4* src;
                if (KDIM == W1IN || kb < W1IN)
                    src = (const float4*)(in1 + (size_t)node * W1IN + kb);
                else
                    src = (const float4*)(in2 + (size_t)node * (KDIM - W1IN) + (kb - W1IN));
                float* xr = X + e * XSTR + hf * 32;
#pragma unroll
                for (int bb = 0; bb < 4; bb++) {
                    float4 x0 = src[2 * bb];
                    float4 x1 = src[2 * bb + 1];
                    *(float2*)&xr[bb * 8 + 0] = make_float2(tf32f(x0.x), tf32f(x1.x));
                    *(float2*)&xr[bb * 8 + 2] = make_float2(tf32f(x0.y), tf32f(x1.y));
                    *(float2*)&xr[bb * 8 + 4] = make_float2(tf32f(x0.z), tf32f(x1.z));
                    *(float2*)&xr[bb * 8 + 6] = make_float2(tf32f(x0.w), tf32f(x1.w));
                }
            }
            __syncwarp();   // this warp's staging visible to itself

#pragma unroll
            for (int s8 = 0; s8 < 8; s8++) {
                const int s = (c0 >> 3) + s8;
                float2 alo = *(const float2*)(xlo + s8 * 8);
                float2 ahi = *(const float2*)(xhi + s8 * 8);
                u32 a0 = __float_as_uint(alo.x), a1 = __float_as_uint(ahi.x);
                u32 a2 = __float_as_uint(alo.y), a3 = __float_as_uint(ahi.y);
#pragma unroll
                for (int gp = 0; gp < 4; gp++) {
                    float4 bv = *(const float4*)&Bp[((s * 4 + gp) * 32 + lane) * 4];
                    mma_tf32(acc[gp * 2 + 0], a0, a1, a2, a3,
                             __float_as_uint(bv.x), __float_as_uint(bv.y));
                    mma_tf32(acc[gp * 2 + 1], a0, a1, a2, a3,
                             __float_as_uint(bv.z), __float_as_uint(bv.w));
                }
            }
        }

        {
            int r0 = tb + warp * 16 + g;
            int r1 = r0 + 8;
#pragma unroll
            for (int gp = 0; gp < 4; gp++) {
                int c0 = gp * 16 + tig * 4;
                float4 v0 = make_float4(acc[gp*2][0]   + bs[c0],
                                        acc[gp*2][1]   + bs[c0+1],
                                        acc[gp*2+1][0] + bs[c0+2],
                                        acc[gp*2+1][1] + bs[c0+3]);
                float4 v1 = make_float4(acc[gp*2][2]   + bs[c0],
                                        acc[gp*2][3]   + bs[c0+1],
                                        acc[gp*2+1][2] + bs[c0+2],
                                        acc[gp*2+1][3] + bs[c0+3]);
                if (DO_SILU) {
                    v0.x = silu(v0.x); v0.y = silu(v0.y); v0.z = silu(v0.z); v0.w = silu(v0.w);
                    v1.x = silu(v1.x); v1.y = silu(v1.y); v1.z = silu(v1.z); v1.w = silu(v1.w);
                }
                if (r0 < N_NODES) {
                    if (!SKIP_OUT) {
                        float* dst = out + (size_t)r0 * HID + yoff + c0;
                        if (DO_RES) {
                            float4 r = *(const float4*)dst;
                            v0.x += r.x; v0.y += r.y; v0.z += r.z; v0.w += r.w;
                        }
                        *(float4*)dst = v0;
                    }
                    if (WRITE_H) {
                        __half2* d = (__half2*)(g_phx + (size_t)r0 * HID + yoff + c0);
                        d[0] = __floats2half2_rn(v0.x, v0.y);
                        d[1] = __floats2half2_rn(v0.z, v0.w);
                    }
                }
                if (r1 < N_NODES) {
                    if (!SKIP_OUT) {
                        float* dst = out + (size_t)r1 * HID + yoff + c0;
                        if (DO_RES) {
                            float4 r = *(const float4*)dst;
                            v1.x += r.x; v1.y += r.y; v1.z += r.z; v1.w += r.w;
                        }
                        *(float4*)dst = v1;
                    }
                    if (WRITE_H) {
                        __half2* d = (__half2*)(g_phx + (size_t)r1 * HID + yoff + c0);
                        d[0] = __floats2half2_rn(v1.x, v1.y);
                        d[1] = __floats2half2_rn(v1.z, v1.w);
                    }
                }
            }
        }
    }
}

// ---------------------------------------------------------------------------
// node_gemm3 (fp32, embeddings only)
// ---------------------------------------------------------------------------
template<int KDIM, int W1IN, int NOUT_TOTAL, bool DO_SILU, bool DO_RES>
__global__ void __launch_bounds__(256, 2) node_gemm3(
    const float* __restrict__ in1, const float* __restrict__ in2,
    const float* __restrict__ W, const float* __restrict__ b,
    float* __restrict__ out)
{
    extern __shared__ float fsmem[];
    float* ws = fsmem;
    float* bs = ws + KDIM * 64;
    float* stg = bs + 64;

    const int tid  = threadIdx.x;
    const int warp = tid >> 5;
    const int lane = tid & 31;
    const int yoff = blockIdx.y * 64;

    for (int i = tid * 4; i < KDIM * 64; i += 1024) {
        int k = i >> 6, j = i & 63;
        *(float4*)&ws[i] = *(const float4*)(W + (size_t)k * NOUT_TOTAL + yoff + j);
    }
    if (tid < 64) bs[tid] = b[yoff + tid];
    __syncthreads();

    float* xs = stg + warp * (64 * 16);
    const int p    = lane >> 2;
    const int q    = lane & 3;
    const int m    = lane >> 1;
    const int half = lane & 1;

    u64 biasr[4];
#pragma unroll
    for (int g = 0; g < 4; g++)
        biasr[g] = packf2(bs[p * 8 + 2 * g], bs[p * 8 + 2 * g + 1]);

    const int gw     = blockIdx.x * 8 + warp;
    const int nwarps = gridDim.x * 8;
    const int ntiles = N_NODES / 16;

    for (int t = gw; t < ntiles; t += nwarps) {
        const int node = t * 16 + m;
        const float* s1 = in1 + (size_t)node * W1IN;
        const float* s2 = (KDIM > W1IN) ? in2 + (size_t)node * (KDIM - W1IN) : nullptr;

        u64 acc[4][4];
#pragma unroll
        for (int d = 0; d < 4; d++)
#pragma unroll
            for (int g = 0; g < 4; g++) acc[d][g] = biasr[g];

#pragma unroll
        for (int c0 = 0; c0 < KDIM; c0 += 64) {
            __syncwarp();
#pragma unroll
            for (int i = 0; i < 8; i++) {
                int kk = c0 + half * 32 + i * 4;
                float4 v;
                if (KDIM == W1IN || kk < W1IN) v = *(const float4*)(s1 + kk);
                else                           v = *(const float4*)(s2 + (kk - W1IN));
                int kl = kk - c0;
                xs[(kl + 0) * 16 + m] = v.x;
                xs[(kl + 1) * 16 + m] = v.y;
                xs[(kl + 2) * 16 + m] = v.z;
                xs[(kl + 3) * 16 + m] = v.w;
            }
            __syncwarp();

#pragma unroll 4
            for (int k = 0; k < 64; k++) {
                float4 xv = *(const float4*)&xs[k * 16 + q * 4];
                const ulonglong2* wp = (const ulonglong2*)(ws + (c0 + k) * 64 + p * 8);
                ulonglong2 wa = wp[0];
                ulonglong2 wb = wp[1];
                u64 xp[4] = {pack2(xv.x), pack2(xv.y), pack2(xv.z), pack2(xv.w)};
#pragma unroll
                for (int d = 0; d < 4; d++) {
                    ffma2(acc[d][0], xp[d], wa.x);
                    ffma2(acc[d][1], xp[d], wa.y);
                    ffma2(acc[d][2], xp[d], wb.x);
                    ffma2(acc[d][3], xp[d], wb.y);
                }
            }
        }

#pragma unroll
        for (int d = 0; d < 4; d++) {
            int nn = t * 16 + q * 4 + d;
            float* dst = out + (size_t)nn * NOUT_TOTAL + yoff + p * 8;
#pragma unroll
            for (int g = 0; g < 2; g++) {
                float2 a = unpack2(acc[d][2 * g]);
                float2 c = unpack2(acc[d][2 * g + 1]);
                float4 v = make_float4(a.x, a.y, c.x, c.y);
                if (DO_SILU) {
                    v.x = silu(v.x); v.y = silu(v.y);
                    v.z = silu(v.z); v.w = silu(v.w);
                }
                if (DO_RES) {
                    float4 r = *(const float4*)(dst + g * 4);
                    v.x += r.x; v.y += r.y; v.z += r.z; v.w += r.w;
                }
                *(float4*)(dst + g * 4) = v;
            }
        }
    }
}

// ---------------------------------------------------------------------------
// Edge kernel: warp-autonomous 16-edge groups; full fp16 gather (g_phx) ->
// silu -> tf32 mma -> writeback -> segmented reduction -> red4 per run.
// ---------------------------------------------------------------------------
#define SM_B2S  128
#define SM_X2   192
#define SM_B2P  (192 + 128 * XSTR)
#define SM_EDGE_FLOATS (SM_B2P + 8 * 4 * 32 * 4)
#define SM_EDGE_BYTES  (SM_EDGE_FLOATS * 4)

__global__ void __launch_bounds__(256, 3)
edge_kernel2(const int2* __restrict__ sedge,
             const __half* __restrict__ Phx,
             const float* __restrict__ W2, const float* __restrict__ b2)
{
    extern __shared__ float sm[];
    int*   idxs = (int*)sm;
    float* b2s  = sm + SM_B2S;
    float* X2   = sm + SM_X2;
    float* B2p  = sm + SM_B2P;

    const int tid  = threadIdx.x;
    const int warp = tid >> 5, lane = tid & 31;
    const int g    = lane >> 2, tig = lane & 3;

    for (int i = tid; i < 8 * 4 * 32; i += 256) {
        int s  = i >> 7;
        int gp = (i >> 5) & 3;
        int ln = i & 31;
        int gg = ln >> 2, tt = ln & 3;
        int k0 = s * 8;
        int nA = gp * 16 + (gg >> 1) * 4 + (gg & 1);
        int nB = nA + 2;
        float4 v;
        v.x = tf32f(W2[(k0 + tt)     * 64 + nA]);
        v.y = tf32f(W2[(k0 + tt + 4) * 64 + nA]);
        v.z = tf32f(W2[(k0 + tt)     * 64 + nB]);
        v.w = tf32f(W2[(k0 + tt + 4) * 64 + nB]);
        *(float4*)&B2p[i * 4] = v;
    }
    if (tid < 64) b2s[tid] = b2[tid];
    __syncthreads();

    int*   widx = idxs + warp * 16;
    float* WX   = X2 + warp * 16 * XSTR;
    const float* xlo = WX + g * XSTR + tig * 2;
    const float* xhi = xlo + 8 * XSTR;
    const int qd = lane & 15;
    const int sp = lane >> 4;

    const int NG = E_EDGES / 16;
    const int gw0 = blockIdx.x * 8 + warp;
    const int gstr = gridDim.x * 8;

    for (int gi = gw0; gi < NG; gi += gstr) {
        // ---- fp16 gather (row + col) + silu -> WX frag-interleaved tf32 ----
        {
            int e = lane >> 1, half = lane & 1;
            int2 rc = sedge[gi * 16 + e];
            if (half == 0) widx[e] = rc.x;
            const uint4* pr = (const uint4*)(Phx + (size_t)rc.x * HID + half * 32);
            const uint4* pc = (const uint4*)(Phx + (size_t)rc.y * HID + 64 + half * 32);
            float* xr = WX + e * XSTR + half * 32;
#pragma unroll
            for (int bb = 0; bb < 4; bb++) {
                uint4 hr = pr[bb];
                uint4 hc = pc[bb];
                float2 r01 = h2f(hr.x), r23 = h2f(hr.y), r45 = h2f(hr.z), r67 = h2f(hr.w);
                float2 c01 = h2f(hc.x), c23 = h2f(hc.y), c45 = h2f(hc.z), c67 = h2f(hc.w);
                *(float2*)&xr[bb * 8 + 0] = make_float2(tf32f(silu(r01.x + c01.x)),
                                                        tf32f(silu(r45.x + c45.x)));
                *(float2*)&xr[bb * 8 + 2] = make_float2(tf32f(silu(r01.y + c01.y)),
                                                        tf32f(silu(r45.y + c45.y)));
                *(float2*)&xr[bb * 8 + 4] = make_float2(tf32f(silu(r23.x + c23.x)),
                                                        tf32f(silu(r67.x + c67.x)));
                *(float2*)&xr[bb * 8 + 6] = make_float2(tf32f(silu(r23.y + c23.y)),
                                                        tf32f(silu(r67.y + c67.y)));
            }
        }
        __syncwarp();

        // ---- MLP2 MMA ----
        float acc[8][4];
#pragma unroll
        for (int a = 0; a < 8; a++)
#pragma unroll
            for (int c = 0; c < 4; c++) acc[a][c] = 0.f;

#pragma unroll
        for (int s = 0; s < 8; s++) {
            float2 alo = *(const float2*)(xlo + s * 8);
            float2 ahi = *(const float2*)(xhi + s * 8);
            u32 a0 = __float_as_uint(alo.x), a1 = __float_as_uint(ahi.x);
            u32 a2 = __float_as_uint(alo.y), a3 = __float_as_uint(ahi.y);
#pragma unroll
            for (int gp = 0; gp < 4; gp++) {
                float4 bv = *(const float4*)&B2p[((s * 4 + gp) * 32 + lane) * 4];
                mma_tf32(acc[gp * 2 + 0], a0, a1, a2, a3,
                         __float_as_uint(bv.x), __float_as_uint(bv.y));
                mma_tf32(acc[gp * 2 + 1], a0, a1, a2, a3,
                         __float_as_uint(bv.z), __float_as_uint(bv.w));
            }
        }
        __syncwarp();

        // ---- write silu(D2 + b2) back into WX rows g, g+8 ----
        {
            float* rlo = WX + g * XSTR;
            float* rhi = WX + (g + 8) * XSTR;
#pragma unroll
            for (int gp = 0; gp < 4; gp++) {
                int c0 = gp * 16 + tig * 4;
                *(float2*)&rlo[c0]     = make_float2(silu(acc[gp*2][0]   + b2s[c0]),
                                                     silu(acc[gp*2][1]   + b2s[c0+1]));
                *(float2*)&rlo[c0 + 2] = make_float2(silu(acc[gp*2+1][0] + b2s[c0+2]),
                                                     silu(acc[gp*2+1][1] + b2s[c0+3]));
                *(float2*)&rhi[c0]     = make_float2(silu(acc[gp*2][2]   + b2s[c0]),
                                                     silu(acc[gp*2][3]   + b2s[c0+1]));
                *(float2*)&rhi[c0 + 2] = make_float2(silu(acc[gp*2+1][2] + b2s[c0+2]),
                                                     silu(acc[gp*2+1][3] + b2s[c0+3]));
            }
        }
        __syncwarp();

        // ---- segmented reduction: lane (qd, sp) walks 8 edges x 4 cols ----
        {
            int e0 = sp * 8;
            int cur = widx[e0];
            const float* r = WX + e0 * XSTR + qd * 4;
            float2 a01 = *(const float2*)(r);
            float2 a23 = *(const float2*)(r + 2);
            float s0 = a01.x, s1 = a01.y, s2 = a23.x, s3 = a23.y;
#pragma unroll
            for (int j = 1; j < 8; j++) {
                int rw = widx[e0 + j];
                const float* rr = WX + (e0 + j) * XSTR + qd * 4;
                float2 b01 = *(const float2*)(rr);
                float2 b23 = *(const float2*)(rr + 2);
                if (rw != cur) {
                    red4(g_agg + (size_t)cur * EH + qd * 4, s0, s1, s2, s3);
                    cur = rw;
                    s0 = b01.x; s1 = b01.y; s2 = b23.x; s3 = b23.y;
                } else {
                    s0 += b01.x; s1 += b01.y; s2 += b23.x; s3 += b23.y;
                }
            }
            red4(g_agg + (size_t)cur * EH + qd * 4, s0, s1, s2, s3);
        }
        __syncwarp();
    }
}

// ---------------------------------------------------------------------------
extern "C" void kernel_launch(void* const* d_in, const int* in_sizes, int n_in,
                              void* d_out, int out_size)
{
    const float* h_in  = (const float*)d_in[0];
    const int*   edges = (const int*)d_in[1];
    const float* W_in  = (const float*)d_in[2];
    const float* b_in  = (const float*)d_in[3];
    const float* eW1   = (const float*)d_in[4];
    const float* eb1   = (const float*)d_in[5];
    const float* eW2   = (const float*)d_in[6];
    const float* eb2   = (const float*)d_in[7];
    const float* nW1   = (const float*)d_in[8];
    const float* nb1   = (const float*)d_in[9];
    const float* nW2   = (const float*)d_in[10];
    const float* nb2   = (const float*)d_in[11];
    const float* W_out = (const float*)d_in[12];
    const float* b_out = (const float*)d_in[13];

    float*  ph;   cudaGetSymbolAddress((void**)&ph,   g_h);
    float*  pag;  cudaGetSymbolAddress((void**)&pag,  g_agg);
    float*  pz;   cudaGetSymbolAddress((void**)&pz,   g_z);
    __half* pphx; cudaGetSymbolAddress((void**)&pphx, g_phx);
    float*  pwc;  cudaGetSymbolAddress((void**)&pwc,  g_wcat);
    float*  pbc;  cudaGetSymbolAddress((void**)&pbc,  g_bcat);
    int2*   pse;  cudaGetSymbolAddress((void**)&pse,  g_sedge);

    auto smem_g3 = [](int kdim) { return (kdim * 64 + 64 + 8 * 64 * 16) * 4; };
    const int sm_ei  = smem_g3(64);
    const int sm_p   = smem_g3(128);
    const int sm_m128 = (64 + 128 * XSTR + 16 * 4 * 32 * 4) * 4;
    const int sm_m192 = (64 + 128 * XSTR + 24 * 4 * 32 * 4) * 4;

    cudaFuncSetAttribute(edge_kernel2, cudaFuncAttributeMaxDynamicSharedMemorySize, SM_EDGE_BYTES);
    cudaFuncSetAttribute(node_mma<128, 128, false, false, true, true, true>,
                         cudaFuncAttributeMaxDynamicSharedMemorySize, sm_m128);
    cudaFuncSetAttribute(node_mma<192, 128, true, false, false, false, false>,
                         cudaFuncAttributeMaxDynamicSharedMemorySize, sm_m192);
    cudaFuncSetAttribute(node_mma<128, 128, false, true, false, false, false>,
                         cudaFuncAttributeMaxDynamicSharedMemorySize, sm_m128);
    cudaFuncSetAttribute(node_gemm3<64, 64, 128, false, false>,
                         cudaFuncAttributeMaxDynamicSharedMemorySize, sm_ei);
    cudaFuncSetAttribute(node_gemm3<128, 128, 64, false, false>,
                         cudaFuncAttributeMaxDynamicSharedMemorySize, sm_p);

    const int EB = (E_EDGES + 255) / 256;

    // Lazily-created fork stream + events (host resources only; created once,
    // before the capture call, so the captured graph is identical every call).
    static cudaStream_t s2 = nullptr;
    static cudaEvent_t ev_fork = nullptr, ev_join = nullptr;
    if (s2 == nullptr) {
        cudaStreamCreateWithFlags(&s2, cudaStreamNonBlocking);
        cudaEventCreateWithFlags(&ev_fork, cudaEventDisableTiming);
        cudaEventCreateWithFlags(&ev_join, cudaEventDisableTiming);
    }

    // ---- fork: edge sort on s2, overlapped with repack/embed_in/P(l0) ----
    cudaEventRecord(ev_fork, 0);
    cudaStreamWaitEvent(s2, ev_fork, 0);
    k_zero_deg<<<SCAN_BLOCKS, 256, 0, s2>>>();
    k_hist<<<EB, 256, 0, s2>>>(edges);
    k_scan1<<<SCAN_BLOCKS, 256, 0, s2>>>();
    k_scan2<<<1, 256, 0, s2>>>();
    k_scan3<<<SCAN_BLOCKS, 256, 0, s2>>>();
    k_sort_scatter<<<EB, 256, 0, s2>>>(edges);
    cudaEventRecord(ev_join, s2);

    // ---- legacy stream: weight repack + embedding_in + P(l=0) ----
    k_repack<<<(L_LAYERS * HID * HID + 255) / 256, 256>>>(eW1, eb1);
    node_gemm3<64, 64, 128, false, false><<<dim3(148, 2), 256, sm_ei>>>(
        h_in, nullptr, W_in, b_in, ph);

    for (int l = 0; l < L_LAYERS; l++) {
        // P = h @ [W1a|W1b] + [b1|0]  (tf32 mma; fp16-only output, zeroes agg)
        node_mma<128, 128, false, false, true, true, true><<<dim3(148, 2), 256, sm_m128>>>(
            ph, nullptr, pwc + l * HID * HID, pbc + l * HID, pz);
        if (l == 0) cudaStreamWaitEvent(0, ev_join, 0);   // sorted edges ready
        edge_kernel2<<<444, 256, SM_EDGE_BYTES>>>(
            pse, pphx, eW2 + l * EH * EH, eb2 + l * EH);
        // z = silu(concat(h, agg) @ nW1 + nb1)  (tf32 mma)
        node_mma<192, 128, true, false, false, false, false><<<dim3(148, 2), 256, sm_m192>>>(
            ph, pag, nW1 + l * (HID + EH) * HID, nb1 + l * HID, pz);
        // h = h + (z @ nW2 + nb2)  (tf32 mma, fp32 residual epilogue)
        node_mma<128, 128, false, true, false, false, false><<<dim3(148, 2), 256, sm_m128>>>(
            pz, nullptr, nW2 + l * HID * HID, nb2 + l * HID, ph);
    }

    // embedding_out (fp32)
    node_gemm3<128, 128, 64, false, false><<<dim3(148, 1), 256, sm_p>>>(
        ph, nullptr, W_out, b_out, (float*)d_out);
}